// round 12
// baseline (speedup 1.0000x reference)
#include <cuda_runtime.h>
#include <cuda_fp16.h>
#include <cstdint>
#include <math.h>

// ---------------- problem constants ----------------
#define BB      2
#define SS      2048
#define DIMD    2048
#define NHH     16
#define QLORA   1536
#define KVLORA  512
#define ROPED   64
#define NOPED   128
#define VHDD    128
#define QKHD    192
#define KVAW    576
#define ROWS    (BB*SS)
#define SCALE_V 0.07216878364870323f

// ---------------- scratch (device globals) ----------------
__device__ float g_qa [ROWS * QLORA];
__device__ float g_kva[ROWS * KVAW];
__device__ uint32_t g_xh  [ROWS * 1024];
__device__ uint32_t g_wh  [2359296];
__device__ uint32_t g_qah [ROWS * 768];
__device__ uint32_t g_kvah[ROWS * 256];
__device__ uint32_t g_aoh [ROWS * 1024];
__device__ uint32_t g_qb  [ROWS * NHH * 96];
__device__ uint32_t g_kb  [ROWS * NHH * 96];
__device__ uint32_t g_vb  [BB * NHH * VHDD * (SS/2)];

// ============================================================================
// helpers
// ============================================================================
__device__ __forceinline__ uint32_t pack_h(float a, float b) {
    uint16_t lo16 = __half_as_ushort(__float2half_rn(a));
    uint16_t hi16 = __half_as_ushort(__float2half_rn(b));
    return (uint32_t)lo16 | ((uint32_t)hi16 << 16);
}
__device__ __forceinline__ void mma_h(float* d, const uint32_t* a, const uint32_t* b) {
    asm volatile(
        "mma.sync.aligned.m16n8k16.row.col.f32.f16.f16.f32 "
        "{%0,%1,%2,%3}, {%4,%5,%6,%7}, {%8,%9}, {%0,%1,%2,%3};"
        : "+f"(d[0]), "+f"(d[1]), "+f"(d[2]), "+f"(d[3])
        : "r"(a[0]), "r"(a[1]), "r"(a[2]), "r"(a[3]), "r"(b[0]), "r"(b[1]));
}
__device__ __forceinline__ uint32_t smem_u32(const void* p) {
    uint32_t a;
    asm("{ .reg .u64 t; cvta.to.shared.u64 t, %1; cvt.u32.u64 %0, t; }" : "=r"(a) : "l"(p));
    return a;
}
__device__ __forceinline__ void ldsm_x4(uint32_t* r, uint32_t saddr) {
    asm volatile("ldmatrix.sync.aligned.m8n8.x4.shared.b16 {%0,%1,%2,%3}, [%4];"
        : "=r"(r[0]), "=r"(r[1]), "=r"(r[2]), "=r"(r[3]) : "r"(saddr));
}

// ============================================================================
// conversion / prep kernels (unchanged)
// ============================================================================
__global__ void cvt_h_k(const float* __restrict__ in, uint32_t* __restrict__ oh, int n4)
{
    int i0 = (blockIdx.x * blockDim.x + threadIdx.x) * 4;
    float4 v[4];
#pragma unroll
    for (int j = 0; j < 4; ++j)
        if (i0 + j < n4) v[j] = *(const float4*)(in + 4 * (size_t)(i0 + j));
#pragma unroll
    for (int j = 0; j < 4; ++j)
        if (i0 + j < n4) {
            uint2 hi;
            hi.x = pack_h(v[j].x, v[j].y);
            hi.y = pack_h(v[j].z, v[j].w);
            *(uint2*)(oh + 2 * (size_t)(i0 + j)) = hi;
        }
}

__global__ __launch_bounds__(256) void rmsnorm_h_k(
    const float* __restrict__ x, const float* __restrict__ w, int stride, int n,
    uint32_t* __restrict__ oh)
{
    const float* row = x + (size_t)blockIdx.x * stride;
    float ss = 0.f;
    for (int i = threadIdx.x * 4; i < n; i += 1024) {
        float4 v = *(const float4*)(row + i);
        ss += v.x * v.x + v.y * v.y + v.z * v.z + v.w * v.w;
    }
#pragma unroll
    for (int off = 16; off; off >>= 1) ss += __shfl_xor_sync(0xffffffffu, ss, off);
    __shared__ float ws[8];
    if ((threadIdx.x & 31) == 0) ws[threadIdx.x >> 5] = ss;
    __syncthreads();
    float tot = 0.f;
#pragma unroll
    for (int i = 0; i < 8; i++) tot += ws[i];
    float r = rsqrtf(tot / (float)n + 1e-6f);
    const int ow = n >> 1;
    for (int i = threadIdx.x * 4; i < n; i += 1024) {
        float4 v  = *(const float4*)(row + i);
        float4 wv = *(const float4*)(w + i);
        v.x *= r * wv.x; v.y *= r * wv.y; v.z *= r * wv.z; v.w *= r * wv.w;
        uint2 hi;
        hi.x = pack_h(v.x, v.y);
        hi.y = pack_h(v.z, v.w);
        *(uint2*)(oh + (size_t)blockIdx.x * ow + (i >> 1)) = hi;
    }
}

__global__ void rope_kpe_bcast_k(const float* __restrict__ kva,
                                 const float* __restrict__ cosd, const float* __restrict__ sind,
                                 uint32_t* __restrict__ kb)
{
    int i = blockIdx.x * blockDim.x + threadIdx.x;
    if (i >= ROWS * 32) return;
    int wp = i & 31;
    int bs = i >> 5;
    int s = bs & (SS - 1);
    float2 v = *(const float2*)(kva + (size_t)bs * KVAW + KVLORA + 2 * wp);
    float c = cosd[s * 32 + wp], sn = sind[s * 32 + wp];
    uint32_t w = pack_h(v.x * c - v.y * sn, v.x * sn + v.y * c);
    uint32_t* dst = kb + (size_t)bs * 1536 + 64 + wp;
#pragma unroll
    for (int h = 0; h < 16; ++h) dst[h * 96] = w;
}

// ============================================================================
// HMMA GEMM (fp16 1-pass): CTA 128x256, 8 warps (2m x 4n), warp tile 64x64,
// K-chunk 32, double-buffered, ldmatrix fragment loads.
// smem: A 128x20w (2560) | B 256x20w (5120) per stage; 2 stages.
// Epilogue modes: 0 plain fp32; 1 q-rope pack; 2 dual qa/kva; 3 kb+V-transpose.
// ============================================================================
#define A_W    2560
#define STAGEW 7680
#define GEMM_SMEM (2*STAGEW*4)

__global__ __launch_bounds__(256, 1) void gemm_hmma(
    const uint32_t* __restrict__ Ah_, int ldaw,
    const uint32_t* __restrict__ Bh_,
    const float* __restrict__ bias,
    float* __restrict__ C, int N, int K,
    int mode,
    const float* __restrict__ cosd, const float* __restrict__ sind,
    uint32_t* __restrict__ qout,
    const float* __restrict__ bias2, float* __restrict__ C2,
    uint32_t* __restrict__ vout)
{
    extern __shared__ uint32_t smw[];
    const int tid  = threadIdx.x;
    const int lane = tid & 31;
    const int wid  = tid >> 5;
    const int warp_m = wid & 1;        // 2 x 64 rows
    const int warp_n = wid >> 1;       // 4 x 64 cols
    const int bm = blockIdx.y * 128;
    const int bn = blockIdx.x * 256;
    const int t = lane & 3;
    const int g = lane >> 2;
    const int ldbw = K >> 1;
    const int nc = K >> 5;

    // ldmatrix lane addressing (byte offsets within stage)
    const int lane15 = lane & 15;
    const int lhi4   = (lane >> 4) * 4;
    const uint32_t sb = smem_u32(smw);
    const uint32_t aoff0 = ((warp_m * 64 + lane15) * 20 + lhi4) * 4;
    const uint32_t boff0 = (A_W + (warp_n * 64 + lane15) * 20 + lhi4) * 4;

    // loaders: A row = tid>>1 (0..127), half=(tid&1); B rows = tid>>1 and +128
    const int alr = tid >> 1;
    const int ahf = (tid & 1) * 8;     // word offset 0 or 8
    const int blr = tid >> 1;
    const int bhf = (tid & 1) * 8;

    float acc[4][8][4];
#pragma unroll
    for (int i = 0; i < 4; i++)
#pragma unroll
        for (int j = 0; j < 8; j++)
#pragma unroll
            for (int k = 0; k < 4; k++) acc[i][j][k] = 0.f;

    uint4 pa[2], pb[4];
    const uint4 z4 = make_uint4(0, 0, 0, 0);

    // ---- prologue: chunk 0
    {
        const uint32_t* arow = Ah_ + (size_t)(bm + alr) * ldaw + ahf;
        pa[0] = *(const uint4*)(arow);
        pa[1] = *(const uint4*)(arow + 4);
#pragma unroll
        for (int i = 0; i < 2; ++i) {
            int row = blr + i * 128;
            bool bv = (bn + row) < N;
            const uint32_t* brow = Bh_ + (size_t)(bn + row) * ldbw + bhf;
            pb[2*i]   = bv ? *(const uint4*)(brow)     : z4;
            pb[2*i+1] = bv ? *(const uint4*)(brow + 4) : z4;
        }
        uint32_t* st = smw;
        *(uint4*)(st + alr * 20 + ahf)     = pa[0];
        *(uint4*)(st + alr * 20 + ahf + 4) = pa[1];
#pragma unroll
        for (int i = 0; i < 2; ++i) {
            int row = blr + i * 128;
            *(uint4*)(st + A_W + row * 20 + bhf)     = pb[2*i];
            *(uint4*)(st + A_W + row * 20 + bhf + 4) = pb[2*i+1];
        }
    }
    __syncthreads();

    for (int ck = 0; ck < nc; ++ck) {
        if (ck + 1 < nc) {
            const int k0w = (ck + 1) << 4;
            const uint32_t* arow = Ah_ + (size_t)(bm + alr) * ldaw + k0w + ahf;
            pa[0] = *(const uint4*)(arow);
            pa[1] = *(const uint4*)(arow + 4);
#pragma unroll
            for (int i = 0; i < 2; ++i) {
                int row = blr + i * 128;
                bool bv = (bn + row) < N;
                const uint32_t* brow = Bh_ + (size_t)(bn + row) * ldbw + k0w + bhf;
                pb[2*i]   = bv ? *(const uint4*)(brow)     : z4;
                pb[2*i+1] = bv ? *(const uint4*)(brow + 4) : z4;
            }
        }
        // ---- compute current stage via ldmatrix
        {
            const uint32_t stb = sb + (ck & 1) * (STAGEW * 4);
#pragma unroll
            for (int k16 = 0; k16 < 2; ++k16) {
                const uint32_t kb4 = k16 * 32;           // kp*4 bytes
                uint32_t bfr[4][4];
#pragma unroll
                for (int ntp = 0; ntp < 4; ++ntp)
                    ldsm_x4(bfr[ntp], stb + boff0 + ntp * 1280 + kb4);
#pragma unroll
                for (int mt = 0; mt < 4; ++mt) {
                    uint32_t ah[4];
                    ldsm_x4(ah, stb + aoff0 + mt * 1280 + kb4);
#pragma unroll
                    for (int ntp = 0; ntp < 4; ++ntp) {
                        uint32_t b0[2] = { bfr[ntp][0], bfr[ntp][2] };
                        uint32_t b1[2] = { bfr[ntp][1], bfr[ntp][3] };
                        mma_h(acc[mt][2*ntp],   ah, b0);
                        mma_h(acc[mt][2*ntp+1], ah, b1);
                    }
                }
            }
        }
        if (ck + 1 < nc) {
            uint32_t* st = smw + ((ck + 1) & 1) * STAGEW;
            *(uint4*)(st + alr * 20 + ahf)     = pa[0];
            *(uint4*)(st + alr * 20 + ahf + 4) = pa[1];
#pragma unroll
            for (int i = 0; i < 2; ++i) {
                int row = blr + i * 128;
                *(uint4*)(st + A_W + row * 20 + bhf)     = pb[2*i];
                *(uint4*)(st + A_W + row * 20 + bhf + 4) = pb[2*i+1];
            }
        }
        __syncthreads();
    }

    uint16_t* st16 = (uint16_t*)smw;   // mode 3: [vcol 128][row 128] fp16

#pragma unroll
    for (int mt = 0; mt < 4; ++mt) {
        int r0 = bm + warp_m * 64 + mt * 16 + g;
        int r1 = r0 + 8;
#pragma unroll
        for (int nt = 0; nt < 8; ++nt) {
            int c = bn + warp_n * 64 + nt * 8 + t * 2;
            if (c >= N) continue;
            float a0 = acc[mt][nt][0], a1 = acc[mt][nt][1];
            float a2 = acc[mt][nt][2], a3 = acc[mt][nt][3];
            if (mode == 0) {
                float2 bv = *(const float2*)(bias + c);
                a0 += bv.x; a1 += bv.y; a2 += bv.x; a3 += bv.y;
                *(float2*)(C + (size_t)r0 * N + c) = make_float2(a0, a1);
                *(float2*)(C + (size_t)r1 * N + c) = make_float2(a2, a3);
            } else if (mode == 1) {
                float2 bv = *(const float2*)(bias + c);
                a0 += bv.x; a1 += bv.y; a2 += bv.x; a3 += bv.y;
                int d = c % 192;
                if (d >= 128) {
                    int ri = (d - 128) >> 1;
                    int s0 = r0 & (SS - 1), s1 = r1 & (SS - 1);
                    float c0 = cosd[s0 * 32 + ri], n0 = sind[s0 * 32 + ri];
                    float c1 = cosd[s1 * 32 + ri], n1 = sind[s1 * 32 + ri];
                    float x0 = a0, y0 = a1, x1 = a2, y1 = a3;
                    a0 = x0 * c0 - y0 * n0;  a1 = x0 * n0 + y0 * c0;
                    a2 = x1 * c1 - y1 * n1;  a3 = x1 * n1 + y1 * c1;
                }
                qout[(size_t)r0 * 1536 + (c >> 1)] = pack_h(a0, a1);
                qout[(size_t)r1 * 1536 + (c >> 1)] = pack_h(a2, a3);
            } else if (mode == 2) {
                if (c < QLORA) {
                    float2 bv = *(const float2*)(bias + c);
                    a0 += bv.x; a1 += bv.y; a2 += bv.x; a3 += bv.y;
                    *(float2*)(C + (size_t)r0 * QLORA + c) = make_float2(a0, a1);
                    *(float2*)(C + (size_t)r1 * QLORA + c) = make_float2(a2, a3);
                } else {
                    int c2 = c - QLORA;
                    float2 bv = *(const float2*)(bias2 + c2);
                    a0 += bv.x; a1 += bv.y; a2 += bv.x; a3 += bv.y;
                    *(float2*)(C2 + (size_t)r0 * KVAW + c2) = make_float2(a0, a1);
                    *(float2*)(C2 + (size_t)r1 * KVAW + c2) = make_float2(a2, a3);
                }
            } else { // mode 3: tile = one head (256 cols): nope -> kb, V -> transpose
                float2 bv = *(const float2*)(bias + c);
                a0 += bv.x; a1 += bv.y; a2 += bv.x; a3 += bv.y;
                int blk = c & 255;
                if (blk < 128) {
                    int hh = c >> 8;
                    qout[(size_t)r0 * 1536 + hh * 96 + (blk >> 1)] = pack_h(a0, a1);
                    qout[(size_t)r1 * 1536 + hh * 96 + (blk >> 1)] = pack_h(a2, a3);
                } else {
                    int cl = c & 127;
                    int rl0 = r0 - bm, rl1 = r1 - bm;
                    st16[(cl + 0) * 128 + rl0] = __half_as_ushort(__float2half_rn(a0));
                    st16[(cl + 1) * 128 + rl0] = __half_as_ushort(__float2half_rn(a1));
                    st16[(cl + 0) * 128 + rl1] = __half_as_ushort(__float2half_rn(a2));
                    st16[(cl + 1) * 128 + rl1] = __half_as_ushort(__float2half_rn(a3));
                }
            }
        }
    }

    if (mode == 3) {
        __syncthreads();
        int h = bn >> 8;
        int b = bm / SS;
        int s0 = bm & (SS - 1);
        int vd = tid >> 1;
        int jp0 = (tid & 1) * 32;
        size_t base = ((size_t)((b * NHH + h) * VHDD + vd)) * (SS / 2) + (s0 >> 1) + jp0;
#pragma unroll
        for (int j = 0; j < 32; ++j) {
            uint32_t lo = st16[vd * 128 + 2 * (jp0 + j)];
            uint32_t hi = st16[vd * 128 + 2 * (jp0 + j) + 1];
            vout[base + j] = lo | (hi << 16);
        }
    }
}

// ============================================================================
// HMMA flash attention (causal), 1-pass fp16, 2 CTAs/SM (unchanged)
// ============================================================================
#define FL_QS   0
#define FL_KS   6400
#define FL_VS   12800
#define FL_PS   17408
#define FL_RM   19712
#define FL_RL   19840
#define FL_WORDS 19968
#define FLASH_SMEM (FL_WORDS*4)

__global__ __launch_bounds__(256, 2) void flash_hmma(
    const uint32_t* __restrict__ qh_,
    const uint32_t* __restrict__ kh_,
    const uint32_t* __restrict__ vh_,
    uint32_t* __restrict__ aoh)
{
    extern __shared__ uint32_t sw[];
    float* redm = (float*)(sw + FL_RM);
    float* redl = (float*)(sw + FL_RL);
    const int tid = threadIdx.x;
    const int lane = tid & 31;
    const int wid = tid >> 5;
    const int wm = wid & 3, wn = wid >> 2;
    const int g = lane >> 2, t = lane & 3;
    const int qt = (int)(gridDim.x - 1) - (int)blockIdx.x;
    const int h = blockIdx.y, b = blockIdx.z;
    const int q0 = qt * 64;
    const int row0 = wm * 16 + g, row1 = row0 + 8;

    {
        int r = tid >> 2, qq = tid & 3;
        size_t gb = ((size_t)((b * SS + q0 + r) * NHH + h)) * 96 + qq * 24;
#pragma unroll
        for (int j = 0; j < 6; ++j)
            *(uint4*)(sw + FL_QS + r * 100 + qq * 24 + j * 4) = *(const uint4*)(qh_ + gb + j * 4);
    }

    float o[8][4];
#pragma unroll
    for (int i = 0; i < 8; i++)
#pragma unroll
        for (int j = 0; j < 4; j++) o[i][j] = 0.f;
    float mold0 = -1e30f, mold1 = -1e30f, ls0 = 0.f, ls1 = 0.f;

    for (int kt = 0; kt <= qt; ++kt) {
        const int k0 = kt * 64;
        __syncthreads();
        {
            int r = tid >> 2, qq = tid & 3;
            size_t gb = ((size_t)((b * SS + k0 + r) * NHH + h)) * 96 + qq * 24;
#pragma unroll
            for (int j = 0; j < 6; ++j)
                *(uint4*)(sw + FL_KS + r * 100 + qq * 24 + j * 4) = *(const uint4*)(kh_ + gb + j * 4);
            int vd = tid >> 1, pt = tid & 1;
            size_t vb = ((size_t)((b * NHH + h) * VHDD + vd)) * (SS / 2) + kt * 32 + pt * 16;
#pragma unroll
            for (int j = 0; j < 4; ++j)
                *(uint4*)(sw + FL_VS + vd * 36 + pt * 16 + j * 4) = *(const uint4*)(vh_ + vb + j * 4);
        }
        __syncthreads();

        float sacc[4][4];
#pragma unroll
        for (int i = 0; i < 4; i++)
#pragma unroll
            for (int j = 0; j < 4; j++) sacc[i][j] = 0.f;
#pragma unroll
        for (int ks = 0; ks < 12; ++ks) {
            int aq = (wm * 16 + g) * 100 + ks * 8 + t;
            uint32_t ah[4];
            ah[0] = sw[FL_QS + aq];       ah[1] = sw[FL_QS + aq + 800];
            ah[2] = sw[FL_QS + aq + 4];   ah[3] = sw[FL_QS + aq + 804];
#pragma unroll
            for (int nt = 0; nt < 4; ++nt) {
                int bi = (wn * 32 + nt * 8 + g) * 100 + ks * 8 + t;
                uint32_t bh[2] = { sw[FL_KS + bi], sw[FL_KS + bi + 4] };
                mma_h(sacc[nt], ah, bh);
            }
        }

        const bool diag = (kt == qt);
#pragma unroll
        for (int nt = 0; nt < 4; ++nt) {
            sacc[nt][0] *= SCALE_V; sacc[nt][1] *= SCALE_V;
            sacc[nt][2] *= SCALE_V; sacc[nt][3] *= SCALE_V;
            if (diag) {
                int c0 = wn * 32 + nt * 8 + 2 * t;
                if (c0 > row0)     sacc[nt][0] = -1e30f;
                if (c0 + 1 > row0) sacc[nt][1] = -1e30f;
                if (c0 > row1)     sacc[nt][2] = -1e30f;
                if (c0 + 1 > row1) sacc[nt][3] = -1e30f;
            }
        }

        float m0 = -1e30f, m1 = -1e30f;
#pragma unroll
        for (int nt = 0; nt < 4; ++nt) {
            m0 = fmaxf(m0, fmaxf(sacc[nt][0], sacc[nt][1]));
            m1 = fmaxf(m1, fmaxf(sacc[nt][2], sacc[nt][3]));
        }
        m0 = fmaxf(m0, __shfl_xor_sync(0xffffffffu, m0, 1));
        m0 = fmaxf(m0, __shfl_xor_sync(0xffffffffu, m0, 2));
        m1 = fmaxf(m1, __shfl_xor_sync(0xffffffffu, m1, 1));
        m1 = fmaxf(m1, __shfl_xor_sync(0xffffffffu, m1, 2));
        if (t == 0) { redm[wn * 64 + row0] = m0; redm[wn * 64 + row1] = m1; }
        __syncthreads();

        float mnew0 = fmaxf(mold0, fmaxf(redm[row0], redm[64 + row0]));
        float mnew1 = fmaxf(mold1, fmaxf(redm[row1], redm[64 + row1]));
        float fac0 = __expf(mold0 - mnew0);
        float fac1 = __expf(mold1 - mnew1);
        mold0 = mnew0; mold1 = mnew1;

        float sum0 = 0.f, sum1 = 0.f;
#pragma unroll
        for (int nt = 0; nt < 4; ++nt) {
            float p0 = __expf(sacc[nt][0] - mnew0);
            float p1 = __expf(sacc[nt][1] - mnew0);
            float p2 = __expf(sacc[nt][2] - mnew1);
            float p3 = __expf(sacc[nt][3] - mnew1);
            sum0 += p0 + p1; sum1 += p2 + p3;
            sw[FL_PS + row0 * 36 + wn * 16 + nt * 4 + t] = pack_h(p0, p1);
            sw[FL_PS + row1 * 36 + wn * 16 + nt * 4 + t] = pack_h(p2, p3);
        }
        sum0 += __shfl_xor_sync(0xffffffffu, sum0, 1);
        sum0 += __shfl_xor_sync(0xffffffffu, sum0, 2);
        sum1 += __shfl_xor_sync(0xffffffffu, sum1, 1);
        sum1 += __shfl_xor_sync(0xffffffffu, sum1, 2);
        if (t == 0) { redl[wn * 64 + row0] = sum0; redl[wn * 64 + row1] = sum1; }

#pragma unroll
        for (int nt = 0; nt < 8; ++nt) {
            o[nt][0] *= fac0; o[nt][1] *= fac0;
            o[nt][2] *= fac1; o[nt][3] *= fac1;
        }
        __syncthreads();

        ls0 = ls0 * fac0 + redl[row0] + redl[64 + row0];
        ls1 = ls1 * fac1 + redl[row1] + redl[64 + row1];

#pragma unroll
        for (int ks = 0; ks < 4; ++ks) {
            int pb = (wm * 16 + g) * 36 + ks * 8 + t;
            uint32_t ah[4];
            ah[0] = sw[FL_PS + pb];       ah[1] = sw[FL_PS + pb + 288];
            ah[2] = sw[FL_PS + pb + 4];   ah[3] = sw[FL_PS + pb + 292];
#pragma unroll
            for (int nt = 0; nt < 8; ++nt) {
                int vi = (wn * 64 + nt * 8 + g) * 36 + ks * 8 + t;
                uint32_t bh[2] = { sw[FL_VS + vi], sw[FL_VS + vi + 4] };
                mma_h(o[nt], ah, bh);
            }
        }
    }

    float inv0 = 1.0f / ls0, inv1 = 1.0f / ls1;
    size_t r0 = (size_t)(b * SS + q0 + row0) * 1024;
    size_t r1 = (size_t)(b * SS + q0 + row1) * 1024;
#pragma unroll
    for (int nt = 0; nt < 8; ++nt) {
        int word = h * 64 + wn * 32 + nt * 4 + t;
        aoh[r0 + word] = pack_h(o[nt][0] * inv0, o[nt][1] * inv0);
        aoh[r1 + word] = pack_h(o[nt][2] * inv1, o[nt][3] * inv1);
    }
}

// ============================================================================
// launch
// ============================================================================
extern "C" void kernel_launch(void* const* d_in, const int* in_sizes, int n_in,
                              void* d_out, int out_size)
{
    const float* x         = (const float*)d_in[0];
    const float* fcos      = (const float*)d_in[1];
    const float* fsin      = (const float*)d_in[2];
    const float* wq_a_w    = (const float*)d_in[3];
    const float* wq_a_b    = (const float*)d_in[4];
    const float* q_norm_w  = (const float*)d_in[5];
    const float* wq_b_w    = (const float*)d_in[6];
    const float* wq_b_b    = (const float*)d_in[7];
    const float* wkv_a_w   = (const float*)d_in[8];
    const float* wkv_a_b   = (const float*)d_in[9];
    const float* kv_norm_w = (const float*)d_in[10];
    const float* wkv_b_w   = (const float*)d_in[11];
    const float* wkv_b_b   = (const float*)d_in[12];
    const float* wo_w      = (const float*)d_in[13];
    const float* wo_b      = (const float*)d_in[14];
    float* out = (float*)d_out;

    float *qa, *kva;
    uint32_t *xh, *wh, *qah, *kvah, *qb, *kb, *vb, *aoh;
    cudaGetSymbolAddress((void**)&qa,   g_qa);
    cudaGetSymbolAddress((void**)&kva,  g_kva);
    cudaGetSymbolAddress((void**)&xh,   g_xh);
    cudaGetSymbolAddress((void**)&wh,   g_wh);
    cudaGetSymbolAddress((void**)&qah,  g_qah);
    cudaGetSymbolAddress((void**)&kvah, g_kvah);
    cudaGetSymbolAddress((void**)&qb,   g_qb);
    cudaGetSymbolAddress((void**)&kb,   g_kb);
    cudaGetSymbolAddress((void**)&vb,   g_vb);
    cudaGetSymbolAddress((void**)&aoh,  g_aoh);

    cudaFuncSetAttribute(gemm_hmma,  cudaFuncAttributeMaxDynamicSharedMemorySize, GEMM_SMEM);
    cudaFuncSetAttribute(flash_hmma, cudaFuncAttributeMaxDynamicSharedMemorySize, FLASH_SMEM);

    #define CVTW(src, dh, n) cvt_h_k<<<((n)/16 + 255)/256, 256>>>(src, dh, (n)/4)

    CVTW(x, xh, ROWS * DIMD);
    CVTW(wq_a_w,  wh,                     QLORA * DIMD);
    CVTW(wkv_a_w, wh + QLORA * (DIMD/2),  KVAW * DIMD);
    // fused gemm1+2: [qa | kva] = x @ [wq_a; wkv_a]^T + biases   (N = 2112)
    gemm_hmma<<<dim3((QLORA + KVAW + 255)/256, ROWS/128), 256, GEMM_SMEM>>>(
        xh, DIMD/2, wh, wq_a_b, qa, QLORA + KVAW, DIMD, 2,
        nullptr, nullptr, nullptr, wkv_a_b, kva, nullptr);
    rmsnorm_h_k<<<ROWS, 256>>>(qa, q_norm_w, QLORA, QLORA, qah);
    rmsnorm_h_k<<<ROWS, 256>>>(kva, kv_norm_w, KVAW, KVLORA, kvah);
    rope_kpe_bcast_k<<<(ROWS*32)/256, 256>>>(kva, fcos, fsin, kb);
    // gemm3: q = qa_n @ wq_b^T + b -> fused rope + fp16 pack into qb
    CVTW(wq_b_w, wh, NHH*QKHD*QLORA);
    gemm_hmma<<<dim3((NHH*QKHD)/256, ROWS/128), 256, GEMM_SMEM>>>(
        qah, QLORA/2, wh, wq_b_b, nullptr, NHH*QKHD, QLORA, 1,
        fcos, fsin, qb, nullptr, nullptr, nullptr);
    // gemm4: kv = kva_n @ wkv_b^T + b -> fused kb-nope pack + V-transpose into vb
    CVTW(wkv_b_w, wh, NHH*(NOPED+VHDD)*KVLORA);
    gemm_hmma<<<dim3((NHH*(NOPED+VHDD))/256, ROWS/128), 256, GEMM_SMEM>>>(
        kvah, KVLORA/2, wh, wkv_b_b, nullptr, NHH*(NOPED+VHDD), KVLORA, 3,
        nullptr, nullptr, kb, nullptr, nullptr, vb);
    // flash attention -> aoh (fp16)
    flash_hmma<<<dim3(SS/64, NHH, BB), 256, FLASH_SMEM>>>(qb, kb, vb, aoh);
    // gemm5: out = ao @ wo^T + b
    CVTW(wo_w, wh, DIMD * NHH*VHDD);
    gemm_hmma<<<dim3(DIMD/256, ROWS/128), 256, GEMM_SMEM>>>(
        aoh, (NHH*VHDD)/2, wh, wo_b, out, DIMD, DIMD, 0,
        nullptr, nullptr, nullptr, nullptr, nullptr, nullptr);
}

// round 13
// speedup vs baseline: 1.0410x; 1.0410x over previous
#include <cuda_runtime.h>
#include <cuda_fp16.h>
#include <cstdint>
#include <math.h>

// ---------------- problem constants ----------------
#define BB      2
#define SS      2048
#define DIMD    2048
#define NHH     16
#define QLORA   1536
#define KVLORA  512
#define ROPED   64
#define NOPED   128
#define VHDD    128
#define QKHD    192
#define KVAW    576
#define ROWS    (BB*SS)
#define SCALE_V 0.07216878364870323f

// ---------------- scratch (device globals) ----------------
__device__ float g_qa [ROWS * QLORA];
__device__ float g_kva[ROWS * KVAW];
__device__ uint32_t g_xh  [ROWS * 1024];
__device__ uint32_t g_wa  [(QLORA + KVAW) * (DIMD/2)];   // wq_a ; wkv_a
__device__ uint32_t g_wqb [(NHH*QKHD) * (QLORA/2)];
__device__ uint32_t g_wkvb[(NHH*(NOPED+VHDD)) * (KVLORA/2)];
__device__ uint32_t g_wo  [DIMD * ((NHH*VHDD)/2)];
__device__ uint32_t g_qah [ROWS * 768];
__device__ uint32_t g_kvah[ROWS * 256];
__device__ uint32_t g_aoh [ROWS * 1024];
__device__ uint32_t g_qb  [ROWS * NHH * 96];
__device__ uint32_t g_kb  [ROWS * NHH * 96];
__device__ uint32_t g_vb  [BB * NHH * VHDD * (SS/2)];

// ============================================================================
// helpers
// ============================================================================
__device__ __forceinline__ uint32_t pack_h(float a, float b) {
    uint16_t lo16 = __half_as_ushort(__float2half_rn(a));
    uint16_t hi16 = __half_as_ushort(__float2half_rn(b));
    return (uint32_t)lo16 | ((uint32_t)hi16 << 16);
}
__device__ __forceinline__ void mma_h(float* d, const uint32_t* a, const uint32_t* b) {
    asm volatile(
        "mma.sync.aligned.m16n8k16.row.col.f32.f16.f16.f32 "
        "{%0,%1,%2,%3}, {%4,%5,%6,%7}, {%8,%9}, {%0,%1,%2,%3};"
        : "+f"(d[0]), "+f"(d[1]), "+f"(d[2]), "+f"(d[3])
        : "r"(a[0]), "r"(a[1]), "r"(a[2]), "r"(a[3]), "r"(b[0]), "r"(b[1]));
}

// ============================================================================
// conversion kernel
// ============================================================================
__global__ void cvt_h_k(const float* __restrict__ in, uint32_t* __restrict__ oh, int n4)
{
    int i0 = (blockIdx.x * blockDim.x + threadIdx.x) * 4;
    float4 v[4];
#pragma unroll
    for (int j = 0; j < 4; ++j)
        if (i0 + j < n4) v[j] = *(const float4*)(in + 4 * (size_t)(i0 + j));
#pragma unroll
    for (int j = 0; j < 4; ++j)
        if (i0 + j < n4) {
            uint2 hi;
            hi.x = pack_h(v[j].x, v[j].y);
            hi.y = pack_h(v[j].z, v[j].w);
            *(uint2*)(oh + 2 * (size_t)(i0 + j)) = hi;
        }
}

// ============================================================================
// fused norm+rope: blocks [0,ROWS): rmsnorm qa; [ROWS,2*ROWS): rmsnorm kva;
// [2*ROWS, 2*ROWS+512): roped k_pe broadcast into kb.
// ============================================================================
__global__ __launch_bounds__(256) void norm_rope_k(
    const float* __restrict__ qa, const float* __restrict__ qnw, uint32_t* __restrict__ qah,
    const float* __restrict__ kva, const float* __restrict__ kvnw, uint32_t* __restrict__ kvah,
    const float* __restrict__ cosd, const float* __restrict__ sind, uint32_t* __restrict__ kb)
{
    int bx = blockIdx.x;
    if (bx >= 2 * ROWS) {
        int i = (bx - 2 * ROWS) * 256 + threadIdx.x;   // < ROWS*32
        int wp = i & 31;
        int bs = i >> 5;
        int s = bs & (SS - 1);
        float2 v = *(const float2*)(kva + (size_t)bs * KVAW + KVLORA + 2 * wp);
        float c = cosd[s * 32 + wp], sn = sind[s * 32 + wp];
        uint32_t w = pack_h(v.x * c - v.y * sn, v.x * sn + v.y * c);
        uint32_t* dst = kb + (size_t)bs * 1536 + 64 + wp;
#pragma unroll
        for (int h = 0; h < 16; ++h) dst[h * 96] = w;
        return;
    }
    const bool isq = bx < ROWS;
    const int rix = isq ? bx : bx - ROWS;
    const float* row = (isq ? qa : kva) + (size_t)rix * (isq ? QLORA : KVAW);
    const float* w   = isq ? qnw : kvnw;
    uint32_t* oh     = isq ? qah : kvah;
    const int n      = isq ? QLORA : KVLORA;

    float ss = 0.f;
    for (int i = threadIdx.x * 4; i < n; i += 1024) {
        float4 v = *(const float4*)(row + i);
        ss += v.x * v.x + v.y * v.y + v.z * v.z + v.w * v.w;
    }
#pragma unroll
    for (int off = 16; off; off >>= 1) ss += __shfl_xor_sync(0xffffffffu, ss, off);
    __shared__ float ws[8];
    if ((threadIdx.x & 31) == 0) ws[threadIdx.x >> 5] = ss;
    __syncthreads();
    float tot = 0.f;
#pragma unroll
    for (int i = 0; i < 8; i++) tot += ws[i];
    float r = rsqrtf(tot / (float)n + 1e-6f);
    const int ow = n >> 1;
    for (int i = threadIdx.x * 4; i < n; i += 1024) {
        float4 v  = *(const float4*)(row + i);
        float4 wv = *(const float4*)(w + i);
        v.x *= r * wv.x; v.y *= r * wv.y; v.z *= r * wv.z; v.w *= r * wv.w;
        uint2 hi;
        hi.x = pack_h(v.x, v.y);
        hi.y = pack_h(v.z, v.w);
        *(uint2*)(oh + (size_t)rix * ow + (i >> 1)) = hi;
    }
}

// ============================================================================
// GEMM core (R11 config): CTA 128x128, 8 warps (2m x 4n), K-chunk 32,
// double-buffered, scalar-LDS fragments, 2 CTAs/SM.
// The body is shared via a macro so gemm_hmma (modes 0/2) and gemm34 (modes 1/3)
// stay in separate kernels with minimal register footprints.
// ============================================================================
#define ASZW   2560
#define STAGEW (2*ASZW)
#define GEMM_SMEM (2*STAGEW*4)

#define GEMM_MAINLOOP(ACC)                                                      \
    uint4 pah[2], pbh[2];                                                       \
    const uint4 z4 = make_uint4(0, 0, 0, 0);                                    \
    {                                                                           \
        const int row0_ = lr, row1_ = lr + 64;                                  \
        pah[0] = *(const uint4*)(Ah_ + (size_t)(bm + row0_) * ldaw + lq * 4);   \
        pah[1] = *(const uint4*)(Ah_ + (size_t)(bm + row1_) * ldaw + lq * 4);   \
        pbh[0] = bv0 ? *(const uint4*)(Bh_ + (size_t)(bn + row0_) * ldbw + lq * 4) : z4; \
        pbh[1] = bv1 ? *(const uint4*)(Bh_ + (size_t)(bn + row1_) * ldbw + lq * 4) : z4; \
        uint32_t* st = smw;                                                     \
        *(uint4*)(st + row0_ * 20 + lq * 4)        = pah[0];                    \
        *(uint4*)(st + row1_ * 20 + lq * 4)        = pah[1];                    \
        *(uint4*)(st + ASZW + row0_ * 20 + lq * 4) = pbh[0];                    \
        *(uint4*)(st + ASZW + row1_ * 20 + lq * 4) = pbh[1];                    \
    }                                                                           \
    __syncthreads();                                                            \
    for (int ck = 0; ck < nc; ++ck) {                                           \
        if (ck + 1 < nc) {                                                      \
            const int k0w = (ck + 1) << 4;                                      \
            pah[0] = *(const uint4*)(Ah_ + (size_t)(bm + lr) * ldaw + k0w + lq * 4);      \
            pah[1] = *(const uint4*)(Ah_ + (size_t)(bm + lr + 64) * ldaw + k0w + lq * 4); \
            pbh[0] = bv0 ? *(const uint4*)(Bh_ + (size_t)(bn + lr) * ldbw + k0w + lq * 4) : z4;      \
            pbh[1] = bv1 ? *(const uint4*)(Bh_ + (size_t)(bn + lr + 64) * ldbw + k0w + lq * 4) : z4; \
        }                                                                       \
        {                                                                       \
            uint32_t* Ah = smw + (ck & 1) * STAGEW;                             \
            uint32_t* Bh = Ah + ASZW;                                           \
            _Pragma("unroll")                                                   \
            for (int k16 = 0; k16 < 2; ++k16) {                                 \
                const int kp = k16 * 8;                                         \
                uint32_t bh[4][2];                                              \
                _Pragma("unroll")                                               \
                for (int nt = 0; nt < 4; ++nt) {                                \
                    int idx = (warp_n * 32 + nt * 8 + g) * 20 + kp + t;         \
                    bh[nt][0] = Bh[idx]; bh[nt][1] = Bh[idx + 4];               \
                }                                                               \
                _Pragma("unroll")                                               \
                for (int mt = 0; mt < 4; ++mt) {                                \
                    int base = (warp_m * 64 + mt * 16 + g) * 20 + kp + t;       \
                    uint32_t ah[4];                                             \
                    ah[0] = Ah[base];     ah[1] = Ah[base + 160];               \
                    ah[2] = Ah[base + 4]; ah[3] = Ah[base + 164];               \
                    _Pragma("unroll")                                           \
                    for (int nt = 0; nt < 4; ++nt)                              \
                        mma_h(ACC[mt][nt], ah, bh[nt]);                         \
                }                                                               \
            }                                                                   \
        }                                                                       \
        if (ck + 1 < nc) {                                                      \
            uint32_t* st = smw + ((ck + 1) & 1) * STAGEW;                       \
            *(uint4*)(st + lr * 20 + lq * 4)               = pah[0];            \
            *(uint4*)(st + (lr + 64) * 20 + lq * 4)        = pah[1];            \
            *(uint4*)(st + ASZW + lr * 20 + lq * 4)        = pbh[0];            \
            *(uint4*)(st + ASZW + (lr + 64) * 20 + lq * 4) = pbh[1];            \
        }                                                                       \
        __syncthreads();                                                        \
    }

#define GEMM_PREAMBLE(NN, KK)                        \
    extern __shared__ uint32_t smw[];                \
    const int tid  = threadIdx.x;                    \
    const int lane = tid & 31;                       \
    const int wid  = tid >> 5;                       \
    const int warp_m = wid & 1;                      \
    const int warp_n = wid >> 1;                     \
    const int bm = blockIdx.y * 128;                 \
    const int bn = blockIdx.x * 128;                 \
    const int t = lane & 3;                          \
    const int g = lane >> 2;                         \
    const int ldbw = (KK) >> 1;                      \
    const int nc = (KK) >> 5;                        \
    const int lr = tid >> 2;                         \
    const int lq = tid & 3;                          \
    const bool bv0 = (bn + lr) < (NN);               \
    const bool bv1 = (bn + lr + 64) < (NN);          \
    float acc[4][4][4];                              \
    _Pragma("unroll")                                \
    for (int i = 0; i < 4; i++)                      \
        _Pragma("unroll")                            \
        for (int j = 0; j < 4; j++)                  \
            _Pragma("unroll")                        \
            for (int k = 0; k < 4; k++) acc[i][j][k] = 0.f;

// ---- gemm_hmma: mode 0 (plain) / mode 2 (dual qa|kva) ----
__global__ __launch_bounds__(256, 2) void gemm_hmma(
    const uint32_t* __restrict__ Ah_, int ldaw,
    const uint32_t* __restrict__ Bh_,
    const float* __restrict__ bias,
    float* __restrict__ C, int N, int K,
    int mode,
    const float* __restrict__ bias2, float* __restrict__ C2)
{
    GEMM_PREAMBLE(N, K)
    GEMM_MAINLOOP(acc)

#pragma unroll
    for (int mt = 0; mt < 4; ++mt) {
        int r0 = bm + warp_m * 64 + mt * 16 + g;
        int r1 = r0 + 8;
#pragma unroll
        for (int nt = 0; nt < 4; ++nt) {
            int c = bn + warp_n * 32 + nt * 8 + t * 2;
            if (c >= N) continue;
            float a0 = acc[mt][nt][0], a1 = acc[mt][nt][1];
            float a2 = acc[mt][nt][2], a3 = acc[mt][nt][3];
            if (mode == 0) {
                float2 bv = *(const float2*)(bias + c);
                a0 += bv.x; a1 += bv.y; a2 += bv.x; a3 += bv.y;
                *(float2*)(C + (size_t)r0 * N + c) = make_float2(a0, a1);
                *(float2*)(C + (size_t)r1 * N + c) = make_float2(a2, a3);
            } else {
                if (c < QLORA) {
                    float2 bv = *(const float2*)(bias + c);
                    a0 += bv.x; a1 += bv.y; a2 += bv.x; a3 += bv.y;
                    *(float2*)(C + (size_t)r0 * QLORA + c) = make_float2(a0, a1);
                    *(float2*)(C + (size_t)r1 * QLORA + c) = make_float2(a2, a3);
                } else {
                    int c2 = c - QLORA;
                    float2 bv = *(const float2*)(bias2 + c2);
                    a0 += bv.x; a1 += bv.y; a2 += bv.x; a3 += bv.y;
                    *(float2*)(C2 + (size_t)r0 * KVAW + c2) = make_float2(a0, a1);
                    *(float2*)(C2 + (size_t)r1 * KVAW + c2) = make_float2(a2, a3);
                }
            }
        }
    }
}

// ---- gemm34: z=0 -> q path (mode 1, rope+pack); z=1 -> kv path (mode 3) ----
__global__ __launch_bounds__(256, 2) void gemm34_hmma(
    const uint32_t* __restrict__ A3, const uint32_t* __restrict__ B3,
    const float* __restrict__ bias3, uint32_t* __restrict__ qb,
    const uint32_t* __restrict__ A4, const uint32_t* __restrict__ B4,
    const float* __restrict__ bias4, uint32_t* __restrict__ kb, uint32_t* __restrict__ vb,
    const float* __restrict__ cosd, const float* __restrict__ sind)
{
    const int z = blockIdx.z;
    if (z == 0 && blockIdx.x >= (NHH * QKHD) / 128) return;
    const uint32_t* Ah_ = z ? A4 : A3;
    const uint32_t* Bh_ = z ? B4 : B3;
    const float* bias   = z ? bias4 : bias3;
    const int ldaw = z ? (KVLORA / 2) : (QLORA / 2);
    const int N    = z ? (NHH * (NOPED + VHDD)) : (NHH * QKHD);
    const int K    = z ? KVLORA : QLORA;

    GEMM_PREAMBLE(N, K)
    GEMM_MAINLOOP(acc)

    uint16_t* st16 = (uint16_t*)smw;   // mode 3 V-transpose buffer
    const bool vhalf = z && ((bn >> 7) & 1);

#pragma unroll
    for (int mt = 0; mt < 4; ++mt) {
        int r0 = bm + warp_m * 64 + mt * 16 + g;
        int r1 = r0 + 8;
#pragma unroll
        for (int nt = 0; nt < 4; ++nt) {
            int c = bn + warp_n * 32 + nt * 8 + t * 2;
            float2 bv = *(const float2*)(bias + c);
            float a0 = acc[mt][nt][0] + bv.x, a1 = acc[mt][nt][1] + bv.y;
            float a2 = acc[mt][nt][2] + bv.x, a3 = acc[mt][nt][3] + bv.y;
            if (z == 0) {
                int d = c % 192;
                if (d >= 128) {
                    int ri = (d - 128) >> 1;
                    int s0 = r0 & (SS - 1), s1 = r1 & (SS - 1);
                    float c0 = cosd[s0 * 32 + ri], n0 = sind[s0 * 32 + ri];
                    float c1 = cosd[s1 * 32 + ri], n1 = sind[s1 * 32 + ri];
                    float x0 = a0, y0 = a1, x1 = a2, y1 = a3;
                    a0 = x0 * c0 - y0 * n0;  a1 = x0 * n0 + y0 * c0;
                    a2 = x1 * c1 - y1 * n1;  a3 = x1 * n1 + y1 * c1;
                }
                qb[(size_t)r0 * 1536 + (c >> 1)] = pack_h(a0, a1);
                qb[(size_t)r1 * 1536 + (c >> 1)] = pack_h(a2, a3);
            } else {
                int blk = c & 255;
                if (blk < 128) {
                    int hh = c >> 8;
                    kb[(size_t)r0 * 1536 + hh * 96 + (blk >> 1)] = pack_h(a0, a1);
                    kb[(size_t)r1 * 1536 + hh * 96 + (blk >> 1)] = pack_h(a2, a3);
                } else {
                    int cl = c & 127;
                    int rl0 = r0 - bm, rl1 = r1 - bm;
                    st16[(cl + 0) * 128 + rl0] = __half_as_ushort(__float2half_rn(a0));
                    st16[(cl + 1) * 128 + rl0] = __half_as_ushort(__float2half_rn(a1));
                    st16[(cl + 0) * 128 + rl1] = __half_as_ushort(__float2half_rn(a2));
                    st16[(cl + 1) * 128 + rl1] = __half_as_ushort(__float2half_rn(a3));
                }
            }
        }
    }

    if (vhalf) {
        __syncthreads();
        int h = bn >> 8;
        int b = bm / SS;
        int s0 = bm & (SS - 1);
        int vd = tid >> 1;
        int jp0 = (tid & 1) * 32;
        size_t base = ((size_t)((b * NHH + h) * VHDD + vd)) * (SS / 2) + (s0 >> 1) + jp0;
#pragma unroll
        for (int j = 0; j < 32; ++j) {
            uint32_t lo = st16[vd * 128 + 2 * (jp0 + j)];
            uint32_t hi = st16[vd * 128 + 2 * (jp0 + j) + 1];
            vb[base + j] = lo | (hi << 16);
        }
    }
}

// ============================================================================
// HMMA flash attention (causal), 1-pass fp16, 2 CTAs/SM (unchanged from R10)
// ============================================================================
#define FL_QS   0
#define FL_KS   6400
#define FL_VS   12800
#define FL_PS   17408
#define FL_RM   19712
#define FL_RL   19840
#define FL_WORDS 19968
#define FLASH_SMEM (FL_WORDS*4)

__global__ __launch_bounds__(256, 2) void flash_hmma(
    const uint32_t* __restrict__ qh_,
    const uint32_t* __restrict__ kh_,
    const uint32_t* __restrict__ vh_,
    uint32_t* __restrict__ aoh)
{
    extern __shared__ uint32_t sw[];
    float* redm = (float*)(sw + FL_RM);
    float* redl = (float*)(sw + FL_RL);
    const int tid = threadIdx.x;
    const int lane = tid & 31;
    const int wid = tid >> 5;
    const int wm = wid & 3, wn = wid >> 2;
    const int g = lane >> 2, t = lane & 3;
    const int qt = (int)(gridDim.x - 1) - (int)blockIdx.x;
    const int h = blockIdx.y, b = blockIdx.z;
    const int q0 = qt * 64;
    const int row0 = wm * 16 + g, row1 = row0 + 8;

    {
        int r = tid >> 2, qq = tid & 3;
        size_t gb = ((size_t)((b * SS + q0 + r) * NHH + h)) * 96 + qq * 24;
#pragma unroll
        for (int j = 0; j < 6; ++j)
            *(uint4*)(sw + FL_QS + r * 100 + qq * 24 + j * 4) = *(const uint4*)(qh_ + gb + j * 4);
    }

    float o[8][4];
#pragma unroll
    for (int i = 0; i < 8; i++)
#pragma unroll
        for (int j = 0; j < 4; j++) o[i][j] = 0.f;
    float mold0 = -1e30f, mold1 = -1e30f, ls0 = 0.f, ls1 = 0.f;

    for (int kt = 0; kt <= qt; ++kt) {
        const int k0 = kt * 64;
        __syncthreads();
        {
            int r = tid >> 2, qq = tid & 3;
            size_t gb = ((size_t)((b * SS + k0 + r) * NHH + h)) * 96 + qq * 24;
#pragma unroll
            for (int j = 0; j < 6; ++j)
                *(uint4*)(sw + FL_KS + r * 100 + qq * 24 + j * 4) = *(const uint4*)(kh_ + gb + j * 4);
            int vd = tid >> 1, pt = tid & 1;
            size_t vb = ((size_t)((b * NHH + h) * VHDD + vd)) * (SS / 2) + kt * 32 + pt * 16;
#pragma unroll
            for (int j = 0; j < 4; ++j)
                *(uint4*)(sw + FL_VS + vd * 36 + pt * 16 + j * 4) = *(const uint4*)(vh_ + vb + j * 4);
        }
        __syncthreads();

        float sacc[4][4];
#pragma unroll
        for (int i = 0; i < 4; i++)
#pragma unroll
            for (int j = 0; j < 4; j++) sacc[i][j] = 0.f;
#pragma unroll
        for (int ks = 0; ks < 12; ++ks) {
            int aq = (wm * 16 + g) * 100 + ks * 8 + t;
            uint32_t ah[4];
            ah[0] = sw[FL_QS + aq];       ah[1] = sw[FL_QS + aq + 800];
            ah[2] = sw[FL_QS + aq + 4];   ah[3] = sw[FL_QS + aq + 804];
#pragma unroll
            for (int nt = 0; nt < 4; ++nt) {
                int bi = (wn * 32 + nt * 8 + g) * 100 + ks * 8 + t;
                uint32_t bh[2] = { sw[FL_KS + bi], sw[FL_KS + bi + 4] };
                mma_h(sacc[nt], ah, bh);
            }
        }

        const bool diag = (kt == qt);
#pragma unroll
        for (int nt = 0; nt < 4; ++nt) {
            sacc[nt][0] *= SCALE_V; sacc[nt][1] *= SCALE_V;
            sacc[nt][2] *= SCALE_V; sacc[nt][3] *= SCALE_V;
            if (diag) {
                int c0 = wn * 32 + nt * 8 + 2 * t;
                if (c0 > row0)     sacc[nt][0] = -1e30f;
                if (c0 + 1 > row0) sacc[nt][1] = -1e30f;
                if (c0 > row1)     sacc[nt][2] = -1e30f;
                if (c0 + 1 > row1) sacc[nt][3] = -1e30f;
            }
        }

        float m0 = -1e30f, m1 = -1e30f;
#pragma unroll
        for (int nt = 0; nt < 4; ++nt) {
            m0 = fmaxf(m0, fmaxf(sacc[nt][0], sacc[nt][1]));
            m1 = fmaxf(m1, fmaxf(sacc[nt][2], sacc[nt][3]));
        }
        m0 = fmaxf(m0, __shfl_xor_sync(0xffffffffu, m0, 1));
        m0 = fmaxf(m0, __shfl_xor_sync(0xffffffffu, m0, 2));
        m1 = fmaxf(m1, __shfl_xor_sync(0xffffffffu, m1, 1));
        m1 = fmaxf(m1, __shfl_xor_sync(0xffffffffu, m1, 2));
        if (t == 0) { redm[wn * 64 + row0] = m0; redm[wn * 64 + row1] = m1; }
        __syncthreads();

        float mnew0 = fmaxf(mold0, fmaxf(redm[row0], redm[64 + row0]));
        float mnew1 = fmaxf(mold1, fmaxf(redm[row1], redm[64 + row1]));
        float fac0 = __expf(mold0 - mnew0);
        float fac1 = __expf(mold1 - mnew1);
        mold0 = mnew0; mold1 = mnew1;

        float sum0 = 0.f, sum1 = 0.f;
#pragma unroll
        for (int nt = 0; nt < 4; ++nt) {
            float p0 = __expf(sacc[nt][0] - mnew0);
            float p1 = __expf(sacc[nt][1] - mnew0);
            float p2 = __expf(sacc[nt][2] - mnew1);
            float p3 = __expf(sacc[nt][3] - mnew1);
            sum0 += p0 + p1; sum1 += p2 + p3;
            sw[FL_PS + row0 * 36 + wn * 16 + nt * 4 + t] = pack_h(p0, p1);
            sw[FL_PS + row1 * 36 + wn * 16 + nt * 4 + t] = pack_h(p2, p3);
        }
        sum0 += __shfl_xor_sync(0xffffffffu, sum0, 1);
        sum0 += __shfl_xor_sync(0xffffffffu, sum0, 2);
        sum1 += __shfl_xor_sync(0xffffffffu, sum1, 1);
        sum1 += __shfl_xor_sync(0xffffffffu, sum1, 2);
        if (t == 0) { redl[wn * 64 + row0] = sum0; redl[wn * 64 + row1] = sum1; }

#pragma unroll
        for (int nt = 0; nt < 8; ++nt) {
            o[nt][0] *= fac0; o[nt][1] *= fac0;
            o[nt][2] *= fac1; o[nt][3] *= fac1;
        }
        __syncthreads();

        ls0 = ls0 * fac0 + redl[row0] + redl[64 + row0];
        ls1 = ls1 * fac1 + redl[row1] + redl[64 + row1];

#pragma unroll
        for (int ks = 0; ks < 4; ++ks) {
            int pb = (wm * 16 + g) * 36 + ks * 8 + t;
            uint32_t ah[4];
            ah[0] = sw[FL_PS + pb];       ah[1] = sw[FL_PS + pb + 288];
            ah[2] = sw[FL_PS + pb + 4];   ah[3] = sw[FL_PS + pb + 292];
#pragma unroll
            for (int nt = 0; nt < 8; ++nt) {
                int vi = (wn * 64 + nt * 8 + g) * 36 + ks * 8 + t;
                uint32_t bh[2] = { sw[FL_VS + vi], sw[FL_VS + vi + 4] };
                mma_h(o[nt], ah, bh);
            }
        }
    }

    float inv0 = 1.0f / ls0, inv1 = 1.0f / ls1;
    size_t r0 = (size_t)(b * SS + q0 + row0) * 1024;
    size_t r1 = (size_t)(b * SS + q0 + row1) * 1024;
#pragma unroll
    for (int nt = 0; nt < 8; ++nt) {
        int word = h * 64 + wn * 32 + nt * 4 + t;
        aoh[r0 + word] = pack_h(o[nt][0] * inv0, o[nt][1] * inv0);
        aoh[r1 + word] = pack_h(o[nt][2] * inv1, o[nt][3] * inv1);
    }
}

// ============================================================================
// launch
// ============================================================================
extern "C" void kernel_launch(void* const* d_in, const int* in_sizes, int n_in,
                              void* d_out, int out_size)
{
    const float* x         = (const float*)d_in[0];
    const float* fcos      = (const float*)d_in[1];
    const float* fsin      = (const float*)d_in[2];
    const float* wq_a_w    = (const float*)d_in[3];
    const float* wq_a_b    = (const float*)d_in[4];
    const float* q_norm_w  = (const float*)d_in[5];
    const float* wq_b_w    = (const float*)d_in[6];
    const float* wq_b_b    = (const float*)d_in[7];
    const float* wkv_a_w   = (const float*)d_in[8];
    const float* wkv_a_b   = (const float*)d_in[9];
    const float* kv_norm_w = (const float*)d_in[10];
    const float* wkv_b_w   = (const float*)d_in[11];
    const float* wkv_b_b   = (const float*)d_in[12];
    const float* wo_w      = (const float*)d_in[13];
    const float* wo_b      = (const float*)d_in[14];
    float* out = (float*)d_out;

    float *qa, *kva;
    uint32_t *xh, *wa, *wqb, *wkvb, *wo16, *qah, *kvah, *qb, *kb, *vb, *aoh;
    cudaGetSymbolAddress((void**)&qa,   g_qa);
    cudaGetSymbolAddress((void**)&kva,  g_kva);
    cudaGetSymbolAddress((void**)&xh,   g_xh);
    cudaGetSymbolAddress((void**)&wa,   g_wa);
    cudaGetSymbolAddress((void**)&wqb,  g_wqb);
    cudaGetSymbolAddress((void**)&wkvb, g_wkvb);
    cudaGetSymbolAddress((void**)&wo16, g_wo);
    cudaGetSymbolAddress((void**)&qah,  g_qah);
    cudaGetSymbolAddress((void**)&kvah, g_kvah);
    cudaGetSymbolAddress((void**)&qb,   g_qb);
    cudaGetSymbolAddress((void**)&kb,   g_kb);
    cudaGetSymbolAddress((void**)&vb,   g_vb);
    cudaGetSymbolAddress((void**)&aoh,  g_aoh);

    cudaFuncSetAttribute(gemm_hmma,   cudaFuncAttributeMaxDynamicSharedMemorySize, GEMM_SMEM);
    cudaFuncSetAttribute(gemm34_hmma, cudaFuncAttributeMaxDynamicSharedMemorySize, GEMM_SMEM);
    cudaFuncSetAttribute(flash_hmma,  cudaFuncAttributeMaxDynamicSharedMemorySize, FLASH_SMEM);

    #define CVTW(src, dh, n) cvt_h_k<<<((n)/16 + 255)/256, 256>>>(src, dh, (n)/4)

    // all conversions up front (independent)
    CVTW(x, xh, ROWS * DIMD);
    CVTW(wq_a_w,  wa,                     QLORA * DIMD);
    CVTW(wkv_a_w, wa + QLORA * (DIMD/2),  KVAW * DIMD);
    CVTW(wq_b_w,  wqb,  NHH*QKHD*QLORA);
    CVTW(wkv_b_w, wkvb, NHH*(NOPED+VHDD)*KVLORA);
    CVTW(wo_w,    wo16, DIMD * NHH*VHDD);

    // fused gemm1+2: [qa | kva] = x @ [wq_a; wkv_a]^T + biases (N = 2112)
    gemm_hmma<<<dim3((QLORA + KVAW + 127)/128, ROWS/128), 256, GEMM_SMEM>>>(
        xh, DIMD/2, wa, wq_a_b, qa, QLORA + KVAW, DIMD, 2, wkv_a_b, kva);

    // fused rmsnorm(qa) + rmsnorm(kva) + roped-kpe broadcast
    norm_rope_k<<<2 * ROWS + (ROWS * 32) / 256, 256>>>(
        qa, q_norm_w, qah, kva, kv_norm_w, kvah, fcos, fsin, kb);

    // fused gemm3+gemm4 (z=0: q rope->qb; z=1: kv -> kb nope + vb transpose)
    gemm34_hmma<<<dim3((NHH*(NOPED+VHDD))/128, ROWS/128, 2), 256, GEMM_SMEM>>>(
        qah, wqb, wq_b_b, qb, kvah, wkvb, wkv_b_b, kb, vb, fcos, fsin);

    // flash attention -> aoh (fp16)
    flash_hmma<<<dim3(SS/64, NHH, BB), 256, FLASH_SMEM>>>(qb, kb, vb, aoh);

    // gemm5: out = ao @ wo^T + b
    gemm_hmma<<<dim3(DIMD/128, ROWS/128), 256, GEMM_SMEM>>>(
        aoh, (NHH*VHDD)/2, wo16, wo_b, out, DIMD, DIMD, 0, nullptr, nullptr);
}

// round 14
// speedup vs baseline: 1.0663x; 1.0243x over previous
#include <cuda_runtime.h>
#include <cuda_fp16.h>
#include <cstdint>
#include <math.h>

// ---------------- problem constants ----------------
#define BB      2
#define SS      2048
#define DIMD    2048
#define NHH     16
#define QLORA   1536
#define KVLORA  512
#define ROPED   64
#define NOPED   128
#define VHDD    128
#define QKHD    192
#define KVAW    576
#define ROWS    (BB*SS)
#define SCALE_V 0.07216878364870323f

// ---------------- scratch (device globals) ----------------
__device__ float g_qa [ROWS * QLORA];
__device__ float g_kva[ROWS * KVAW];
__device__ uint32_t g_xh  [ROWS * 1024];
__device__ uint32_t g_wa  [(QLORA + KVAW) * (DIMD/2)];
__device__ uint32_t g_wqb [(NHH*QKHD) * (QLORA/2)];
__device__ uint32_t g_wkvb[(NHH*(NOPED+VHDD)) * (KVLORA/2)];
__device__ uint32_t g_wo  [DIMD * ((NHH*VHDD)/2)];
__device__ uint32_t g_qah [ROWS * 768];
__device__ uint32_t g_kvah[ROWS * 256];
__device__ uint32_t g_aoh [ROWS * 1024];
__device__ uint32_t g_qb  [ROWS * NHH * 96];
__device__ uint32_t g_kb  [ROWS * NHH * 96];
__device__ uint32_t g_vb  [BB * NHH * VHDD * (SS/2)];

// ============================================================================
// helpers
// ============================================================================
__device__ __forceinline__ uint32_t pack_h(float a, float b) {
    uint16_t lo16 = __half_as_ushort(__float2half_rn(a));
    uint16_t hi16 = __half_as_ushort(__float2half_rn(b));
    return (uint32_t)lo16 | ((uint32_t)hi16 << 16);
}
__device__ __forceinline__ void mma_h(float* d, const uint32_t* a, const uint32_t* b) {
    asm volatile(
        "mma.sync.aligned.m16n8k16.row.col.f32.f16.f16.f32 "
        "{%0,%1,%2,%3}, {%4,%5,%6,%7}, {%8,%9}, {%0,%1,%2,%3};"
        : "+f"(d[0]), "+f"(d[1]), "+f"(d[2]), "+f"(d[3])
        : "r"(a[0]), "r"(a[1]), "r"(a[2]), "r"(a[3]), "r"(b[0]), "r"(b[1]));
}

// ============================================================================
// merged conversion kernel: 6 segments, each exact multiple of 1024 float4/blk
// blocks: x 2048 | wq_a 768 | wkv_a 288 | wq_b 1152 | wkv_b 512 | wo 1024
// ============================================================================
#define CB0 2048
#define CB1 (CB0+768)
#define CB2 (CB1+288)
#define CB3 (CB2+1152)
#define CB4 (CB3+512)
#define CB5 (CB4+1024)

__global__ void cvt_all_k(
    const float* __restrict__ s0, uint32_t* __restrict__ d0,
    const float* __restrict__ s1, uint32_t* __restrict__ d1,
    const float* __restrict__ s2, uint32_t* __restrict__ d2,
    const float* __restrict__ s3, uint32_t* __restrict__ d3,
    const float* __restrict__ s4, uint32_t* __restrict__ d4,
    const float* __restrict__ s5, uint32_t* __restrict__ d5)
{
    cudaGridDependencySynchronize();
    int b = blockIdx.x;
    const float* src; uint32_t* dst; int base;
    if      (b < CB0) { src = s0; dst = d0; base = 0;   }
    else if (b < CB1) { src = s1; dst = d1; base = CB0; }
    else if (b < CB2) { src = s2; dst = d2; base = CB1; }
    else if (b < CB3) { src = s3; dst = d3; base = CB2; }
    else if (b < CB4) { src = s4; dst = d4; base = CB3; }
    else              { src = s5; dst = d5; base = CB4; }
    size_t i0 = ((size_t)(b - base) * 256 + threadIdx.x) * 4;
    float4 v[4];
#pragma unroll
    for (int j = 0; j < 4; ++j) v[j] = *(const float4*)(src + 4 * (i0 + j));
#pragma unroll
    for (int j = 0; j < 4; ++j) {
        uint2 hi;
        hi.x = pack_h(v[j].x, v[j].y);
        hi.y = pack_h(v[j].z, v[j].w);
        *(uint2*)(dst + 2 * (i0 + j)) = hi;
    }
}

// ============================================================================
// fused norm+rope (unchanged math)
// ============================================================================
__global__ __launch_bounds__(256) void norm_rope_k(
    const float* __restrict__ qa, const float* __restrict__ qnw, uint32_t* __restrict__ qah,
    const float* __restrict__ kva, const float* __restrict__ kvnw, uint32_t* __restrict__ kvah,
    const float* __restrict__ cosd, const float* __restrict__ sind, uint32_t* __restrict__ kb)
{
    cudaGridDependencySynchronize();
    int bx = blockIdx.x;
    if (bx >= 2 * ROWS) {
        int i = (bx - 2 * ROWS) * 256 + threadIdx.x;
        int wp = i & 31;
        int bs = i >> 5;
        int s = bs & (SS - 1);
        float2 v = *(const float2*)(kva + (size_t)bs * KVAW + KVLORA + 2 * wp);
        float c = cosd[s * 32 + wp], sn = sind[s * 32 + wp];
        uint32_t w = pack_h(v.x * c - v.y * sn, v.x * sn + v.y * c);
        uint32_t* dst = kb + (size_t)bs * 1536 + 64 + wp;
#pragma unroll
        for (int h = 0; h < 16; ++h) dst[h * 96] = w;
        return;
    }
    const bool isq = bx < ROWS;
    const int rix = isq ? bx : bx - ROWS;
    const float* row = (isq ? qa : kva) + (size_t)rix * (isq ? QLORA : KVAW);
    const float* w   = isq ? qnw : kvnw;
    uint32_t* oh     = isq ? qah : kvah;
    const int n      = isq ? QLORA : KVLORA;

    float ss = 0.f;
    for (int i = threadIdx.x * 4; i < n; i += 1024) {
        float4 v = *(const float4*)(row + i);
        ss += v.x * v.x + v.y * v.y + v.z * v.z + v.w * v.w;
    }
#pragma unroll
    for (int off = 16; off; off >>= 1) ss += __shfl_xor_sync(0xffffffffu, ss, off);
    __shared__ float ws[8];
    if ((threadIdx.x & 31) == 0) ws[threadIdx.x >> 5] = ss;
    __syncthreads();
    float tot = 0.f;
#pragma unroll
    for (int i = 0; i < 8; i++) tot += ws[i];
    float r = rsqrtf(tot / (float)n + 1e-6f);
    const int ow = n >> 1;
    for (int i = threadIdx.x * 4; i < n; i += 1024) {
        float4 v  = *(const float4*)(row + i);
        float4 wv = *(const float4*)(w + i);
        v.x *= r * wv.x; v.y *= r * wv.y; v.z *= r * wv.z; v.w *= r * wv.w;
        uint2 hi;
        hi.x = pack_h(v.x, v.y);
        hi.y = pack_h(v.z, v.w);
        *(uint2*)(oh + (size_t)rix * ow + (i >> 1)) = hi;
    }
}

// ============================================================================
// GEMM core (R11/R13 config): CTA 128x128, 8 warps (2m x 4n), K-chunk 32,
// double-buffered, 2 CTAs/SM. bm/bn provided by the caller kernel.
// ============================================================================
#define ASZW   2560
#define STAGEW (2*ASZW)
#define GEMM_SMEM (2*STAGEW*4)

#define GEMM_MAINLOOP(ACC)                                                      \
    uint4 pah[2], pbh[2];                                                       \
    const uint4 z4 = make_uint4(0, 0, 0, 0);                                    \
    {                                                                           \
        const int row0_ = lr, row1_ = lr + 64;                                  \
        pah[0] = *(const uint4*)(Ah_ + (size_t)(bm + row0_) * ldaw + lq * 4);   \
        pah[1] = *(const uint4*)(Ah_ + (size_t)(bm + row1_) * ldaw + lq * 4);   \
        pbh[0] = bv0 ? *(const uint4*)(Bh_ + (size_t)(bn + row0_) * ldbw + lq * 4) : z4; \
        pbh[1] = bv1 ? *(const uint4*)(Bh_ + (size_t)(bn + row1_) * ldbw + lq * 4) : z4; \
        uint32_t* st = smw;                                                     \
        *(uint4*)(st + row0_ * 20 + lq * 4)        = pah[0];                    \
        *(uint4*)(st + row1_ * 20 + lq * 4)        = pah[1];                    \
        *(uint4*)(st + ASZW + row0_ * 20 + lq * 4) = pbh[0];                    \
        *(uint4*)(st + ASZW + row1_ * 20 + lq * 4) = pbh[1];                    \
    }                                                                           \
    __syncthreads();                                                            \
    for (int ck = 0; ck < nc; ++ck) {                                           \
        if (ck + 1 < nc) {                                                      \
            const int k0w = (ck + 1) << 4;                                      \
            pah[0] = *(const uint4*)(Ah_ + (size_t)(bm + lr) * ldaw + k0w + lq * 4);      \
            pah[1] = *(const uint4*)(Ah_ + (size_t)(bm + lr + 64) * ldaw + k0w + lq * 4); \
            pbh[0] = bv0 ? *(const uint4*)(Bh_ + (size_t)(bn + lr) * ldbw + k0w + lq * 4) : z4;      \
            pbh[1] = bv1 ? *(const uint4*)(Bh_ + (size_t)(bn + lr + 64) * ldbw + k0w + lq * 4) : z4; \
        }                                                                       \
        {                                                                       \
            uint32_t* Ah = smw + (ck & 1) * STAGEW;                             \
            uint32_t* Bh = Ah + ASZW;                                           \
            _Pragma("unroll")                                                   \
            for (int k16 = 0; k16 < 2; ++k16) {                                 \
                const int kp = k16 * 8;                                         \
                uint32_t bh[4][2];                                              \
                _Pragma("unroll")                                               \
                for (int nt = 0; nt < 4; ++nt) {                                \
                    int idx = (warp_n * 32 + nt * 8 + g) * 20 + kp + t;         \
                    bh[nt][0] = Bh[idx]; bh[nt][1] = Bh[idx + 4];               \
                }                                                               \
                _Pragma("unroll")                                               \
                for (int mt = 0; mt < 4; ++mt) {                                \
                    int base = (warp_m * 64 + mt * 16 + g) * 20 + kp + t;       \
                    uint32_t ah[4];                                             \
                    ah[0] = Ah[base];     ah[1] = Ah[base + 160];               \
                    ah[2] = Ah[base + 4]; ah[3] = Ah[base + 164];               \
                    _Pragma("unroll")                                           \
                    for (int nt = 0; nt < 4; ++nt)                              \
                        mma_h(ACC[mt][nt], ah, bh[nt]);                         \
                }                                                               \
            }                                                                   \
        }                                                                       \
        if (ck + 1 < nc) {                                                      \
            uint32_t* st = smw + ((ck + 1) & 1) * STAGEW;                       \
            *(uint4*)(st + lr * 20 + lq * 4)               = pah[0];            \
            *(uint4*)(st + (lr + 64) * 20 + lq * 4)        = pah[1];            \
            *(uint4*)(st + ASZW + lr * 20 + lq * 4)        = pbh[0];            \
            *(uint4*)(st + ASZW + (lr + 64) * 20 + lq * 4) = pbh[1];            \
        }                                                                       \
        __syncthreads();                                                        \
    }

#define GEMM_PREAMBLE(NN, KK)                        \
    extern __shared__ uint32_t smw[];                \
    const int tid  = threadIdx.x;                    \
    const int lane = tid & 31;                       \
    const int wid  = tid >> 5;                       \
    const int warp_m = wid & 1;                      \
    const int warp_n = wid >> 1;                     \
    const int t = lane & 3;                          \
    const int g = lane >> 2;                         \
    const int ldbw = (KK) >> 1;                      \
    const int nc = (KK) >> 5;                        \
    const int lr = tid >> 2;                         \
    const int lq = tid & 3;                          \
    const bool bv0 = (bn + lr) < (NN);               \
    const bool bv1 = (bn + lr + 64) < (NN);          \
    float acc[4][4][4];                              \
    _Pragma("unroll")                                \
    for (int i = 0; i < 4; i++)                      \
        _Pragma("unroll")                            \
        for (int j = 0; j < 4; j++)                  \
            _Pragma("unroll")                        \
            for (int k = 0; k < 4; k++) acc[i][j][k] = 0.f;

// ---- gemm_hmma: mode 0 (plain) / mode 2 (dual qa|kva) ----
__global__ __launch_bounds__(256, 2) void gemm_hmma(
    const uint32_t* __restrict__ Ah_, int ldaw,
    const uint32_t* __restrict__ Bh_,
    const float* __restrict__ bias,
    float* __restrict__ C, int N, int K,
    int mode,
    const float* __restrict__ bias2, float* __restrict__ C2)
{
    cudaGridDependencySynchronize();
    const int bm = blockIdx.y * 128;
    const int bn = blockIdx.x * 128;
    GEMM_PREAMBLE(N, K)
    GEMM_MAINLOOP(acc)

#pragma unroll
    for (int mt = 0; mt < 4; ++mt) {
        int r0 = bm + warp_m * 64 + mt * 16 + g;
        int r1 = r0 + 8;
#pragma unroll
        for (int nt = 0; nt < 4; ++nt) {
            int c = bn + warp_n * 32 + nt * 8 + t * 2;
            if (c >= N) continue;
            float a0 = acc[mt][nt][0], a1 = acc[mt][nt][1];
            float a2 = acc[mt][nt][2], a3 = acc[mt][nt][3];
            if (mode == 0) {
                float2 bv = *(const float2*)(bias + c);
                a0 += bv.x; a1 += bv.y; a2 += bv.x; a3 += bv.y;
                *(float2*)(C + (size_t)r0 * N + c) = make_float2(a0, a1);
                *(float2*)(C + (size_t)r1 * N + c) = make_float2(a2, a3);
            } else {
                if (c < QLORA) {
                    float2 bv = *(const float2*)(bias + c);
                    a0 += bv.x; a1 += bv.y; a2 += bv.x; a3 += bv.y;
                    *(float2*)(C + (size_t)r0 * QLORA + c) = make_float2(a0, a1);
                    *(float2*)(C + (size_t)r1 * QLORA + c) = make_float2(a2, a3);
                } else {
                    int c2 = c - QLORA;
                    float2 bv = *(const float2*)(bias2 + c2);
                    a0 += bv.x; a1 += bv.y; a2 += bv.x; a3 += bv.y;
                    *(float2*)(C2 + (size_t)r0 * KVAW + c2) = make_float2(a0, a1);
                    *(float2*)(C2 + (size_t)r1 * KVAW + c2) = make_float2(a2, a3);
                }
            }
        }
    }
}

// ---- gemm34: flattened 1D grid; bid<768 -> q path; else kv path ----
__global__ __launch_bounds__(256, 2) void gemm34_hmma(
    const uint32_t* __restrict__ A3, const uint32_t* __restrict__ B3,
    const float* __restrict__ bias3, uint32_t* __restrict__ qb,
    const uint32_t* __restrict__ A4, const uint32_t* __restrict__ B4,
    const float* __restrict__ bias4, uint32_t* __restrict__ kb, uint32_t* __restrict__ vb,
    const float* __restrict__ cosd, const float* __restrict__ sind)
{
    cudaGridDependencySynchronize();
    const int bid = blockIdx.x;
    const int z = (bid >= 768);
    int bx, by;
    if (!z) { bx = bid % 24; by = bid / 24; }
    else    { int r = bid - 768; bx = r & 31; by = r >> 5; }
    const int bm = by * 128;
    const int bn = bx * 128;

    const uint32_t* Ah_ = z ? A4 : A3;
    const uint32_t* Bh_ = z ? B4 : B3;
    const float* bias   = z ? bias4 : bias3;
    const int ldaw = z ? (KVLORA / 2) : (QLORA / 2);
    const int N    = z ? (NHH * (NOPED + VHDD)) : (NHH * QKHD);
    const int K    = z ? KVLORA : QLORA;

    GEMM_PREAMBLE(N, K)
    GEMM_MAINLOOP(acc)

    uint16_t* st16 = (uint16_t*)smw;
    const bool vhalf = z && ((bn >> 7) & 1);

#pragma unroll
    for (int mt = 0; mt < 4; ++mt) {
        int r0 = bm + warp_m * 64 + mt * 16 + g;
        int r1 = r0 + 8;
#pragma unroll
        for (int nt = 0; nt < 4; ++nt) {
            int c = bn + warp_n * 32 + nt * 8 + t * 2;
            float2 bv = *(const float2*)(bias + c);
            float a0 = acc[mt][nt][0] + bv.x, a1 = acc[mt][nt][1] + bv.y;
            float a2 = acc[mt][nt][2] + bv.x, a3 = acc[mt][nt][3] + bv.y;
            if (!z) {
                int d = c % 192;
                if (d >= 128) {
                    int ri = (d - 128) >> 1;
                    int s0 = r0 & (SS - 1), s1 = r1 & (SS - 1);
                    float c0 = cosd[s0 * 32 + ri], n0 = sind[s0 * 32 + ri];
                    float c1 = cosd[s1 * 32 + ri], n1 = sind[s1 * 32 + ri];
                    float x0 = a0, y0 = a1, x1 = a2, y1 = a3;
                    a0 = x0 * c0 - y0 * n0;  a1 = x0 * n0 + y0 * c0;
                    a2 = x1 * c1 - y1 * n1;  a3 = x1 * n1 + y1 * c1;
                }
                qb[(size_t)r0 * 1536 + (c >> 1)] = pack_h(a0, a1);
                qb[(size_t)r1 * 1536 + (c >> 1)] = pack_h(a2, a3);
            } else {
                int blk = c & 255;
                if (blk < 128) {
                    int hh = c >> 8;
                    kb[(size_t)r0 * 1536 + hh * 96 + (blk >> 1)] = pack_h(a0, a1);
                    kb[(size_t)r1 * 1536 + hh * 96 + (blk >> 1)] = pack_h(a2, a3);
                } else {
                    int cl = c & 127;
                    int rl0 = r0 - bm, rl1 = r1 - bm;
                    st16[(cl + 0) * 128 + rl0] = __half_as_ushort(__float2half_rn(a0));
                    st16[(cl + 1) * 128 + rl0] = __half_as_ushort(__float2half_rn(a1));
                    st16[(cl + 0) * 128 + rl1] = __half_as_ushort(__float2half_rn(a2));
                    st16[(cl + 1) * 128 + rl1] = __half_as_ushort(__float2half_rn(a3));
                }
            }
        }
    }

    if (vhalf) {
        __syncthreads();
        int h = bn >> 8;
        int b = bm / SS;
        int s0 = bm & (SS - 1);
        int vd = tid >> 1;
        int jp0 = (tid & 1) * 32;
        size_t base = ((size_t)((b * NHH + h) * VHDD + vd)) * (SS / 2) + (s0 >> 1) + jp0;
#pragma unroll
        for (int j = 0; j < 32; ++j) {
            uint32_t lo = st16[vd * 128 + 2 * (jp0 + j)];
            uint32_t hi = st16[vd * 128 + 2 * (jp0 + j) + 1];
            vb[base + j] = lo | (hi << 16);
        }
    }
}

// ============================================================================
// HMMA flash attention (causal), 1-pass fp16, 2 CTAs/SM (unchanged math)
// ============================================================================
#define FL_QS   0
#define FL_KS   6400
#define FL_VS   12800
#define FL_PS   17408
#define FL_RM   19712
#define FL_RL   19840
#define FL_WORDS 19968
#define FLASH_SMEM (FL_WORDS*4)

__global__ __launch_bounds__(256, 2) void flash_hmma(
    const uint32_t* __restrict__ qh_,
    const uint32_t* __restrict__ kh_,
    const uint32_t* __restrict__ vh_,
    uint32_t* __restrict__ aoh)
{
    cudaGridDependencySynchronize();
    extern __shared__ uint32_t sw[];
    float* redm = (float*)(sw + FL_RM);
    float* redl = (float*)(sw + FL_RL);
    const int tid = threadIdx.x;
    const int lane = tid & 31;
    const int wid = tid >> 5;
    const int wm = wid & 3, wn = wid >> 2;
    const int g = lane >> 2, t = lane & 3;
    const int qt = (int)(gridDim.x - 1) - (int)blockIdx.x;
    const int h = blockIdx.y, b = blockIdx.z;
    const int q0 = qt * 64;
    const int row0 = wm * 16 + g, row1 = row0 + 8;

    {
        int r = tid >> 2, qq = tid & 3;
        size_t gb = ((size_t)((b * SS + q0 + r) * NHH + h)) * 96 + qq * 24;
#pragma unroll
        for (int j = 0; j < 6; ++j)
            *(uint4*)(sw + FL_QS + r * 100 + qq * 24 + j * 4) = *(const uint4*)(qh_ + gb + j * 4);
    }

    float o[8][4];
#pragma unroll
    for (int i = 0; i < 8; i++)
#pragma unroll
        for (int j = 0; j < 4; j++) o[i][j] = 0.f;
    float mold0 = -1e30f, mold1 = -1e30f, ls0 = 0.f, ls1 = 0.f;

    for (int kt = 0; kt <= qt; ++kt) {
        const int k0 = kt * 64;
        __syncthreads();
        {
            int r = tid >> 2, qq = tid & 3;
            size_t gb = ((size_t)((b * SS + k0 + r) * NHH + h)) * 96 + qq * 24;
#pragma unroll
            for (int j = 0; j < 6; ++j)
                *(uint4*)(sw + FL_KS + r * 100 + qq * 24 + j * 4) = *(const uint4*)(kh_ + gb + j * 4);
            int vd = tid >> 1, pt = tid & 1;
            size_t vb = ((size_t)((b * NHH + h) * VHDD + vd)) * (SS / 2) + kt * 32 + pt * 16;
#pragma unroll
            for (int j = 0; j < 4; ++j)
                *(uint4*)(sw + FL_VS + vd * 36 + pt * 16 + j * 4) = *(const uint4*)(vh_ + vb + j * 4);
        }
        __syncthreads();

        float sacc[4][4];
#pragma unroll
        for (int i = 0; i < 4; i++)
#pragma unroll
            for (int j = 0; j < 4; j++) sacc[i][j] = 0.f;
#pragma unroll
        for (int ks = 0; ks < 12; ++ks) {
            int aq = (wm * 16 + g) * 100 + ks * 8 + t;
            uint32_t ah[4];
            ah[0] = sw[FL_QS + aq];       ah[1] = sw[FL_QS + aq + 800];
            ah[2] = sw[FL_QS + aq + 4];   ah[3] = sw[FL_QS + aq + 804];
#pragma unroll
            for (int nt = 0; nt < 4; ++nt) {
                int bi = (wn * 32 + nt * 8 + g) * 100 + ks * 8 + t;
                uint32_t bh[2] = { sw[FL_KS + bi], sw[FL_KS + bi + 4] };
                mma_h(sacc[nt], ah, bh);
            }
        }

        const bool diag = (kt == qt);
#pragma unroll
        for (int nt = 0; nt < 4; ++nt) {
            sacc[nt][0] *= SCALE_V; sacc[nt][1] *= SCALE_V;
            sacc[nt][2] *= SCALE_V; sacc[nt][3] *= SCALE_V;
            if (diag) {
                int c0 = wn * 32 + nt * 8 + 2 * t;
                if (c0 > row0)     sacc[nt][0] = -1e30f;
                if (c0 + 1 > row0) sacc[nt][1] = -1e30f;
                if (c0 > row1)     sacc[nt][2] = -1e30f;
                if (c0 + 1 > row1) sacc[nt][3] = -1e30f;
            }
        }

        float m0 = -1e30f, m1 = -1e30f;
#pragma unroll
        for (int nt = 0; nt < 4; ++nt) {
            m0 = fmaxf(m0, fmaxf(sacc[nt][0], sacc[nt][1]));
            m1 = fmaxf(m1, fmaxf(sacc[nt][2], sacc[nt][3]));
        }
        m0 = fmaxf(m0, __shfl_xor_sync(0xffffffffu, m0, 1));
        m0 = fmaxf(m0, __shfl_xor_sync(0xffffffffu, m0, 2));
        m1 = fmaxf(m1, __shfl_xor_sync(0xffffffffu, m1, 1));
        m1 = fmaxf(m1, __shfl_xor_sync(0xffffffffu, m1, 2));
        if (t == 0) { redm[wn * 64 + row0] = m0; redm[wn * 64 + row1] = m1; }
        __syncthreads();

        float mnew0 = fmaxf(mold0, fmaxf(redm[row0], redm[64 + row0]));
        float mnew1 = fmaxf(mold1, fmaxf(redm[row1], redm[64 + row1]));
        float fac0 = __expf(mold0 - mnew0);
        float fac1 = __expf(mold1 - mnew1);
        mold0 = mnew0; mold1 = mnew1;

        float sum0 = 0.f, sum1 = 0.f;
#pragma unroll
        for (int nt = 0; nt < 4; ++nt) {
            float p0 = __expf(sacc[nt][0] - mnew0);
            float p1 = __expf(sacc[nt][1] - mnew0);
            float p2 = __expf(sacc[nt][2] - mnew1);
            float p3 = __expf(sacc[nt][3] - mnew1);
            sum0 += p0 + p1; sum1 += p2 + p3;
            sw[FL_PS + row0 * 36 + wn * 16 + nt * 4 + t] = pack_h(p0, p1);
            sw[FL_PS + row1 * 36 + wn * 16 + nt * 4 + t] = pack_h(p2, p3);
        }
        sum0 += __shfl_xor_sync(0xffffffffu, sum0, 1);
        sum0 += __shfl_xor_sync(0xffffffffu, sum0, 2);
        sum1 += __shfl_xor_sync(0xffffffffu, sum1, 1);
        sum1 += __shfl_xor_sync(0xffffffffu, sum1, 2);
        if (t == 0) { redl[wn * 64 + row0] = sum0; redl[wn * 64 + row1] = sum1; }

#pragma unroll
        for (int nt = 0; nt < 8; ++nt) {
            o[nt][0] *= fac0; o[nt][1] *= fac0;
            o[nt][2] *= fac1; o[nt][3] *= fac1;
        }
        __syncthreads();

        ls0 = ls0 * fac0 + redl[row0] + redl[64 + row0];
        ls1 = ls1 * fac1 + redl[row1] + redl[64 + row1];

#pragma unroll
        for (int ks = 0; ks < 4; ++ks) {
            int pb = (wm * 16 + g) * 36 + ks * 8 + t;
            uint32_t ah[4];
            ah[0] = sw[FL_PS + pb];       ah[1] = sw[FL_PS + pb + 288];
            ah[2] = sw[FL_PS + pb + 4];   ah[3] = sw[FL_PS + pb + 292];
#pragma unroll
            for (int nt = 0; nt < 8; ++nt) {
                int vi = (wn * 64 + nt * 8 + g) * 36 + ks * 8 + t;
                uint32_t bh[2] = { sw[FL_VS + vi], sw[FL_VS + vi + 4] };
                mma_h(o[nt], ah, bh);
            }
        }
    }

    float inv0 = 1.0f / ls0, inv1 = 1.0f / ls1;
    size_t r0 = (size_t)(b * SS + q0 + row0) * 1024;
    size_t r1 = (size_t)(b * SS + q0 + row1) * 1024;
#pragma unroll
    for (int nt = 0; nt < 8; ++nt) {
        int word = h * 64 + wn * 32 + nt * 4 + t;
        aoh[r0 + word] = pack_h(o[nt][0] * inv0, o[nt][1] * inv0);
        aoh[r1 + word] = pack_h(o[nt][2] * inv1, o[nt][3] * inv1);
    }
}

// ============================================================================
// launch (all kernels with PDL attribute)
// ============================================================================
extern "C" void kernel_launch(void* const* d_in, const int* in_sizes, int n_in,
                              void* d_out, int out_size)
{
    const float* x         = (const float*)d_in[0];
    const float* fcos      = (const float*)d_in[1];
    const float* fsin      = (const float*)d_in[2];
    const float* wq_a_w    = (const float*)d_in[3];
    const float* wq_a_b    = (const float*)d_in[4];
    const float* q_norm_w  = (const float*)d_in[5];
    const float* wq_b_w    = (const float*)d_in[6];
    const float* wq_b_b    = (const float*)d_in[7];
    const float* wkv_a_w   = (const float*)d_in[8];
    const float* wkv_a_b   = (const float*)d_in[9];
    const float* kv_norm_w = (const float*)d_in[10];
    const float* wkv_b_w   = (const float*)d_in[11];
    const float* wkv_b_b   = (const float*)d_in[12];
    const float* wo_w      = (const float*)d_in[13];
    const float* wo_b      = (const float*)d_in[14];
    float* out = (float*)d_out;

    float *qa, *kva;
    uint32_t *xh, *wa, *wqb, *wkvb, *wo16, *qah, *kvah, *qb, *kb, *vb, *aoh;
    cudaGetSymbolAddress((void**)&qa,   g_qa);
    cudaGetSymbolAddress((void**)&kva,  g_kva);
    cudaGetSymbolAddress((void**)&xh,   g_xh);
    cudaGetSymbolAddress((void**)&wa,   g_wa);
    cudaGetSymbolAddress((void**)&wqb,  g_wqb);
    cudaGetSymbolAddress((void**)&wkvb, g_wkvb);
    cudaGetSymbolAddress((void**)&wo16, g_wo);
    cudaGetSymbolAddress((void**)&qah,  g_qah);
    cudaGetSymbolAddress((void**)&kvah, g_kvah);
    cudaGetSymbolAddress((void**)&qb,   g_qb);
    cudaGetSymbolAddress((void**)&kb,   g_kb);
    cudaGetSymbolAddress((void**)&vb,   g_vb);
    cudaGetSymbolAddress((void**)&aoh,  g_aoh);

    cudaFuncSetAttribute(gemm_hmma,   cudaFuncAttributeMaxDynamicSharedMemorySize, GEMM_SMEM);
    cudaFuncSetAttribute(gemm34_hmma, cudaFuncAttributeMaxDynamicSharedMemorySize, GEMM_SMEM);
    cudaFuncSetAttribute(flash_hmma,  cudaFuncAttributeMaxDynamicSharedMemorySize, FLASH_SMEM);

    cudaLaunchAttribute at;
    at.id = cudaLaunchAttributeProgrammaticStreamSerialization;
    at.val.programmaticStreamSerializationAllowed = 1;

    cudaLaunchConfig_t cfg = {};
    cfg.blockDim = dim3(256, 1, 1);
    cfg.stream = 0;
    cfg.attrs = &at;
    cfg.numAttrs = 1;

    // 1) all fp32->fp16 conversions (one launch)
    cfg.gridDim = dim3(CB5, 1, 1);
    cfg.dynamicSmemBytes = 0;
    cudaLaunchKernelEx(&cfg, cvt_all_k,
        x, xh, wq_a_w, wa, wkv_a_w, (uint32_t*)(wa + QLORA * (DIMD/2)),
        wq_b_w, wqb, wkv_b_w, wkvb, wo_w, wo16);

    // 2) fused gemm1+2
    cfg.gridDim = dim3((QLORA + KVAW + 127) / 128, ROWS / 128, 1);
    cfg.dynamicSmemBytes = GEMM_SMEM;
    cudaLaunchKernelEx(&cfg, gemm_hmma,
        (const uint32_t*)xh, (int)(DIMD/2), (const uint32_t*)wa, wq_a_b,
        qa, (int)(QLORA + KVAW), (int)DIMD, 2, wkv_a_b, kva);

    // 3) fused rmsnorm + roped-kpe broadcast
    cfg.gridDim = dim3(2 * ROWS + (ROWS * 32) / 256, 1, 1);
    cfg.dynamicSmemBytes = 0;
    cudaLaunchKernelEx(&cfg, norm_rope_k,
        (const float*)qa, q_norm_w, qah, (const float*)kva, kv_norm_w, kvah,
        fcos, fsin, kb);

    // 4) fused gemm3+gemm4 (1792 useful CTAs)
    cfg.gridDim = dim3(768 + 1024, 1, 1);
    cfg.dynamicSmemBytes = GEMM_SMEM;
    cudaLaunchKernelEx(&cfg, gemm34_hmma,
        (const uint32_t*)qah, (const uint32_t*)wqb, wq_b_b, qb,
        (const uint32_t*)kvah, (const uint32_t*)wkvb, wkv_b_b, kb, vb,
        fcos, fsin);

    // 5) flash attention
    cfg.gridDim = dim3(SS / 64, NHH, BB);
    cfg.dynamicSmemBytes = FLASH_SMEM;
    cudaLaunchKernelEx(&cfg, flash_hmma,
        (const uint32_t*)qb, (const uint32_t*)kb, (const uint32_t*)vb, aoh);

    // 6) gemm5
    cfg.gridDim = dim3(DIMD / 128, ROWS / 128, 1);
    cfg.dynamicSmemBytes = GEMM_SMEM;
    cudaLaunchKernelEx(&cfg, gemm_hmma,
        (const uint32_t*)aoh, (int)((NHH*VHDD)/2), (const uint32_t*)wo16, wo_b,
        out, (int)DIMD, (int)DIMD, 0, (const float*)nullptr, (float*)nullptr);
}

// round 15
// speedup vs baseline: 1.1656x; 1.0932x over previous
#include <cuda_runtime.h>
#include <cuda_fp16.h>
#include <cstdint>
#include <math.h>

// ---------------- problem constants ----------------
#define BB      2
#define SS      2048
#define DIMD    2048
#define NHH     16
#define QLORA   1536
#define KVLORA  512
#define ROPED   64
#define NOPED   128
#define VHDD    128
#define QKHD    192
#define KVAW    576
#define ROWS    (BB*SS)
#define SCALE_V 0.07216878364870323f

// ---------------- scratch (device globals) ----------------
__device__ float g_qa [ROWS * QLORA];
__device__ float g_kva[ROWS * KVAW];
__device__ uint32_t g_xh  [ROWS * 1024];
__device__ uint32_t g_wa  [(QLORA + KVAW) * (DIMD/2)];
__device__ uint32_t g_wqb [(NHH*QKHD) * (QLORA/2)];
__device__ uint32_t g_wkvb[(NHH*(NOPED+VHDD)) * (KVLORA/2)];
__device__ uint32_t g_wo  [DIMD * ((NHH*VHDD)/2)];
__device__ uint32_t g_qah [ROWS * 768];
__device__ uint32_t g_kvah[ROWS * 256];
__device__ uint32_t g_aoh [ROWS * 1024];
__device__ uint32_t g_qb  [ROWS * NHH * 96];
__device__ uint32_t g_kb  [ROWS * NHH * 96];
__device__ uint32_t g_vb  [BB * NHH * VHDD * (SS/2)];

// ============================================================================
// helpers
// ============================================================================
__device__ __forceinline__ uint32_t pack_h(float a, float b) {
    uint16_t lo16 = __half_as_ushort(__float2half_rn(a));
    uint16_t hi16 = __half_as_ushort(__float2half_rn(b));
    return (uint32_t)lo16 | ((uint32_t)hi16 << 16);
}
__device__ __forceinline__ void mma_h(float* d, const uint32_t* a, const uint32_t* b) {
    asm volatile(
        "mma.sync.aligned.m16n8k16.row.col.f32.f16.f16.f32 "
        "{%0,%1,%2,%3}, {%4,%5,%6,%7}, {%8,%9}, {%0,%1,%2,%3};"
        : "+f"(d[0]), "+f"(d[1]), "+f"(d[2]), "+f"(d[3])
        : "r"(a[0]), "r"(a[1]), "r"(a[2]), "r"(a[3]), "r"(b[0]), "r"(b[1]));
}
__device__ __forceinline__ uint32_t smem_u32(const void* p) {
    uint32_t a;
    asm("{ .reg .u64 t; cvta.to.shared.u64 t, %1; cvt.u32.u64 %0, t; }" : "=r"(a) : "l"(p));
    return a;
}
#define CP16(dst, src, sz) \
    asm volatile("cp.async.ca.shared.global [%0], [%1], 16, %2;" :: "r"(dst), "l"(src), "r"(sz))
#define CP_COMMIT() asm volatile("cp.async.commit_group;")
#define CP_WAIT1()  asm volatile("cp.async.wait_group 1;" ::: "memory")

// ============================================================================
// merged conversion kernel (unchanged)
// ============================================================================
#define CB0 2048
#define CB1 (CB0+768)
#define CB2 (CB1+288)
#define CB3 (CB2+1152)
#define CB4 (CB3+512)
#define CB5 (CB4+1024)

__global__ void cvt_all_k(
    const float* __restrict__ s0, uint32_t* __restrict__ d0,
    const float* __restrict__ s1, uint32_t* __restrict__ d1,
    const float* __restrict__ s2, uint32_t* __restrict__ d2,
    const float* __restrict__ s3, uint32_t* __restrict__ d3,
    const float* __restrict__ s4, uint32_t* __restrict__ d4,
    const float* __restrict__ s5, uint32_t* __restrict__ d5)
{
    cudaGridDependencySynchronize();
    int b = blockIdx.x;
    const float* src; uint32_t* dst; int base;
    if      (b < CB0) { src = s0; dst = d0; base = 0;   }
    else if (b < CB1) { src = s1; dst = d1; base = CB0; }
    else if (b < CB2) { src = s2; dst = d2; base = CB1; }
    else if (b < CB3) { src = s3; dst = d3; base = CB2; }
    else if (b < CB4) { src = s4; dst = d4; base = CB3; }
    else              { src = s5; dst = d5; base = CB4; }
    size_t i0 = ((size_t)(b - base) * 256 + threadIdx.x) * 4;
    float4 v[4];
#pragma unroll
    for (int j = 0; j < 4; ++j) v[j] = *(const float4*)(src + 4 * (i0 + j));
#pragma unroll
    for (int j = 0; j < 4; ++j) {
        uint2 hi;
        hi.x = pack_h(v[j].x, v[j].y);
        hi.y = pack_h(v[j].z, v[j].w);
        *(uint2*)(dst + 2 * (i0 + j)) = hi;
    }
}

// ============================================================================
// fused norm+rope (unchanged math)
// ============================================================================
__global__ __launch_bounds__(256) void norm_rope_k(
    const float* __restrict__ qa, const float* __restrict__ qnw, uint32_t* __restrict__ qah,
    const float* __restrict__ kva, const float* __restrict__ kvnw, uint32_t* __restrict__ kvah,
    const float* __restrict__ cosd, const float* __restrict__ sind, uint32_t* __restrict__ kb)
{
    cudaGridDependencySynchronize();
    int bx = blockIdx.x;
    if (bx >= 2 * ROWS) {
        int i = (bx - 2 * ROWS) * 256 + threadIdx.x;
        int wp = i & 31;
        int bs = i >> 5;
        int s = bs & (SS - 1);
        float2 v = *(const float2*)(kva + (size_t)bs * KVAW + KVLORA + 2 * wp);
        float c = cosd[s * 32 + wp], sn = sind[s * 32 + wp];
        uint32_t w = pack_h(v.x * c - v.y * sn, v.x * sn + v.y * c);
        uint32_t* dst = kb + (size_t)bs * 1536 + 64 + wp;
#pragma unroll
        for (int h = 0; h < 16; ++h) dst[h * 96] = w;
        return;
    }
    const bool isq = bx < ROWS;
    const int rix = isq ? bx : bx - ROWS;
    const float* row = (isq ? qa : kva) + (size_t)rix * (isq ? QLORA : KVAW);
    const float* w   = isq ? qnw : kvnw;
    uint32_t* oh     = isq ? qah : kvah;
    const int n      = isq ? QLORA : KVLORA;

    float ss = 0.f;
    for (int i = threadIdx.x * 4; i < n; i += 1024) {
        float4 v = *(const float4*)(row + i);
        ss += v.x * v.x + v.y * v.y + v.z * v.z + v.w * v.w;
    }
#pragma unroll
    for (int off = 16; off; off >>= 1) ss += __shfl_xor_sync(0xffffffffu, ss, off);
    __shared__ float ws[8];
    if ((threadIdx.x & 31) == 0) ws[threadIdx.x >> 5] = ss;
    __syncthreads();
    float tot = 0.f;
#pragma unroll
    for (int i = 0; i < 8; i++) tot += ws[i];
    float r = rsqrtf(tot / (float)n + 1e-6f);
    const int ow = n >> 1;
    for (int i = threadIdx.x * 4; i < n; i += 1024) {
        float4 v  = *(const float4*)(row + i);
        float4 wv = *(const float4*)(w + i);
        v.x *= r * wv.x; v.y *= r * wv.y; v.z *= r * wv.z; v.w *= r * wv.w;
        uint2 hi;
        hi.x = pack_h(v.x, v.y);
        hi.y = pack_h(v.z, v.w);
        *(uint2*)(oh + (size_t)rix * ow + (i >> 1)) = hi;
    }
}

// ============================================================================
// GEMM core: CTA 128x128, 8 warps (2m x 4n), K-chunk 32, cp.async 3-stage,
// 2 CTAs/SM.
// ============================================================================
#define ASZW   2560
#define STAGEW (2*ASZW)
#define GEMM_SMEM (3*STAGEW*4)

#define GEMM_ISSUE(S, CK) do {                                   \
    uint32_t stb_ = sbB + (uint32_t)(S) * (STAGEW * 4);          \
    int k0w_ = (CK) << 4;                                        \
    CP16(stb_ + adst0, ar0 + k0w_, 16u);                         \
    CP16(stb_ + adst1, ar1 + k0w_, 16u);                         \
    CP16(stb_ + bdst0, br0 + k0w_, sz0);                         \
    CP16(stb_ + bdst1, br1 + k0w_, sz1);                         \
} while (0)

#define GEMM_MAINLOOP(ACC)                                                      \
    const uint32_t sbB = smem_u32(smw);                                         \
    const uint32_t adst0 = (lr * 20 + lq * 4) * 4;                              \
    const uint32_t adst1 = ((lr + 64) * 20 + lq * 4) * 4;                       \
    const uint32_t bdst0 = (ASZW + lr * 20 + lq * 4) * 4;                       \
    const uint32_t bdst1 = (ASZW + (lr + 64) * 20 + lq * 4) * 4;                \
    const uint32_t* ar0 = Ah_ + (size_t)(bm + lr) * ldaw + lq * 4;              \
    const uint32_t* ar1 = Ah_ + (size_t)(bm + lr + 64) * ldaw + lq * 4;         \
    const uint32_t* br0 = Bh_ + (size_t)(bv0 ? (bn + lr) : 0) * ldbw + lq * 4;  \
    const uint32_t* br1 = Bh_ + (size_t)(bv1 ? (bn + lr + 64) : 0) * ldbw + lq * 4; \
    const uint32_t sz0 = bv0 ? 16u : 0u, sz1 = bv1 ? 16u : 0u;                  \
    GEMM_ISSUE(0, 0); CP_COMMIT();                                              \
    if (nc > 1) { GEMM_ISSUE(1, 1); } CP_COMMIT();                              \
    CP_WAIT1(); __syncthreads();                                                \
    for (int ck = 0; ck < nc; ++ck) {                                           \
        {                                                                       \
            uint32_t* Ah = smw + (ck % 3) * STAGEW;                             \
            uint32_t* Bh = Ah + ASZW;                                           \
            _Pragma("unroll")                                                   \
            for (int k16 = 0; k16 < 2; ++k16) {                                 \
                const int kp = k16 * 8;                                         \
                uint32_t bh[4][2];                                              \
                _Pragma("unroll")                                               \
                for (int nt = 0; nt < 4; ++nt) {                                \
                    int idx = (warp_n * 32 + nt * 8 + g) * 20 + kp + t;         \
                    bh[nt][0] = Bh[idx]; bh[nt][1] = Bh[idx + 4];               \
                }                                                               \
                _Pragma("unroll")                                               \
                for (int mt = 0; mt < 4; ++mt) {                                \
                    int base = (warp_m * 64 + mt * 16 + g) * 20 + kp + t;       \
                    uint32_t ah[4];                                             \
                    ah[0] = Ah[base];     ah[1] = Ah[base + 160];               \
                    ah[2] = Ah[base + 4]; ah[3] = Ah[base + 164];               \
                    _Pragma("unroll")                                           \
                    for (int nt = 0; nt < 4; ++nt)                              \
                        mma_h(ACC[mt][nt], ah, bh[nt]);                         \
                }                                                               \
            }                                                                   \
        }                                                                       \
        if (ck + 2 < nc) { GEMM_ISSUE((ck + 2) % 3, ck + 2); }                  \
        CP_COMMIT(); CP_WAIT1();                                                \
        __syncthreads();                                                        \
    }

#define GEMM_PREAMBLE(NN, KK)                        \
    extern __shared__ uint32_t smw[];                \
    const int tid  = threadIdx.x;                    \
    const int lane = tid & 31;                       \
    const int wid  = tid >> 5;                       \
    const int warp_m = wid & 1;                      \
    const int warp_n = wid >> 1;                     \
    const int t = lane & 3;                          \
    const int g = lane >> 2;                         \
    const int ldbw = (KK) >> 1;                      \
    const int nc = (KK) >> 5;                        \
    const int lr = tid >> 2;                         \
    const int lq = tid & 3;                          \
    const bool bv0 = (bn + lr) < (NN);               \
    const bool bv1 = (bn + lr + 64) < (NN);          \
    float acc[4][4][4];                              \
    _Pragma("unroll")                                \
    for (int i = 0; i < 4; i++)                      \
        _Pragma("unroll")                            \
        for (int j = 0; j < 4; j++)                  \
            _Pragma("unroll")                        \
            for (int k = 0; k < 4; k++) acc[i][j][k] = 0.f;

// ---- gemm_hmma: mode 0 (plain) / mode 2 (dual qa|kva) ----
__global__ __launch_bounds__(256, 2) void gemm_hmma(
    const uint32_t* __restrict__ Ah_, int ldaw,
    const uint32_t* __restrict__ Bh_,
    const float* __restrict__ bias,
    float* __restrict__ C, int N, int K,
    int mode,
    const float* __restrict__ bias2, float* __restrict__ C2)
{
    cudaGridDependencySynchronize();
    const int bm = blockIdx.y * 128;
    const int bn = blockIdx.x * 128;
    GEMM_PREAMBLE(N, K)
    GEMM_MAINLOOP(acc)

#pragma unroll
    for (int mt = 0; mt < 4; ++mt) {
        int r0 = bm + warp_m * 64 + mt * 16 + g;
        int r1 = r0 + 8;
#pragma unroll
        for (int nt = 0; nt < 4; ++nt) {
            int c = bn + warp_n * 32 + nt * 8 + t * 2;
            if (c >= N) continue;
            float a0 = acc[mt][nt][0], a1 = acc[mt][nt][1];
            float a2 = acc[mt][nt][2], a3 = acc[mt][nt][3];
            if (mode == 0) {
                float2 bv = *(const float2*)(bias + c);
                a0 += bv.x; a1 += bv.y; a2 += bv.x; a3 += bv.y;
                *(float2*)(C + (size_t)r0 * N + c) = make_float2(a0, a1);
                *(float2*)(C + (size_t)r1 * N + c) = make_float2(a2, a3);
            } else {
                if (c < QLORA) {
                    float2 bv = *(const float2*)(bias + c);
                    a0 += bv.x; a1 += bv.y; a2 += bv.x; a3 += bv.y;
                    *(float2*)(C + (size_t)r0 * QLORA + c) = make_float2(a0, a1);
                    *(float2*)(C + (size_t)r1 * QLORA + c) = make_float2(a2, a3);
                } else {
                    int c2 = c - QLORA;
                    float2 bv = *(const float2*)(bias2 + c2);
                    a0 += bv.x; a1 += bv.y; a2 += bv.x; a3 += bv.y;
                    *(float2*)(C2 + (size_t)r0 * KVAW + c2) = make_float2(a0, a1);
                    *(float2*)(C2 + (size_t)r1 * KVAW + c2) = make_float2(a2, a3);
                }
            }
        }
    }
}

// ---- gemm34: flattened 1D grid; bid<768 -> q path; else kv path ----
__global__ __launch_bounds__(256, 2) void gemm34_hmma(
    const uint32_t* __restrict__ A3, const uint32_t* __restrict__ B3,
    const float* __restrict__ bias3, uint32_t* __restrict__ qb,
    const uint32_t* __restrict__ A4, const uint32_t* __restrict__ B4,
    const float* __restrict__ bias4, uint32_t* __restrict__ kb, uint32_t* __restrict__ vb,
    const float* __restrict__ cosd, const float* __restrict__ sind)
{
    cudaGridDependencySynchronize();
    const int bid = blockIdx.x;
    const int z = (bid >= 768);
    int bx, by;
    if (!z) { bx = bid % 24; by = bid / 24; }
    else    { int r = bid - 768; bx = r & 31; by = r >> 5; }
    const int bm = by * 128;
    const int bn = bx * 128;

    const uint32_t* Ah_ = z ? A4 : A3;
    const uint32_t* Bh_ = z ? B4 : B3;
    const float* bias   = z ? bias4 : bias3;
    const int ldaw = z ? (KVLORA / 2) : (QLORA / 2);
    const int N    = z ? (NHH * (NOPED + VHDD)) : (NHH * QKHD);
    const int K    = z ? KVLORA : QLORA;

    GEMM_PREAMBLE(N, K)
    GEMM_MAINLOOP(acc)

    uint16_t* st16 = (uint16_t*)smw;
    const bool vhalf = z && ((bn >> 7) & 1);

#pragma unroll
    for (int mt = 0; mt < 4; ++mt) {
        int r0 = bm + warp_m * 64 + mt * 16 + g;
        int r1 = r0 + 8;
#pragma unroll
        for (int nt = 0; nt < 4; ++nt) {
            int c = bn + warp_n * 32 + nt * 8 + t * 2;
            float2 bv = *(const float2*)(bias + c);
            float a0 = acc[mt][nt][0] + bv.x, a1 = acc[mt][nt][1] + bv.y;
            float a2 = acc[mt][nt][2] + bv.x, a3 = acc[mt][nt][3] + bv.y;
            if (!z) {
                int d = c % 192;
                if (d >= 128) {
                    int ri = (d - 128) >> 1;
                    int s0 = r0 & (SS - 1), s1 = r1 & (SS - 1);
                    float c0 = cosd[s0 * 32 + ri], n0 = sind[s0 * 32 + ri];
                    float c1 = cosd[s1 * 32 + ri], n1 = sind[s1 * 32 + ri];
                    float x0 = a0, y0 = a1, x1 = a2, y1 = a3;
                    a0 = x0 * c0 - y0 * n0;  a1 = x0 * n0 + y0 * c0;
                    a2 = x1 * c1 - y1 * n1;  a3 = x1 * n1 + y1 * c1;
                }
                qb[(size_t)r0 * 1536 + (c >> 1)] = pack_h(a0, a1);
                qb[(size_t)r1 * 1536 + (c >> 1)] = pack_h(a2, a3);
            } else {
                int blk = c & 255;
                if (blk < 128) {
                    int hh = c >> 8;
                    kb[(size_t)r0 * 1536 + hh * 96 + (blk >> 1)] = pack_h(a0, a1);
                    kb[(size_t)r1 * 1536 + hh * 96 + (blk >> 1)] = pack_h(a2, a3);
                } else {
                    int cl = c & 127;
                    int rl0 = r0 - bm, rl1 = r1 - bm;
                    st16[(cl + 0) * 128 + rl0] = __half_as_ushort(__float2half_rn(a0));
                    st16[(cl + 1) * 128 + rl0] = __half_as_ushort(__float2half_rn(a1));
                    st16[(cl + 0) * 128 + rl1] = __half_as_ushort(__float2half_rn(a2));
                    st16[(cl + 1) * 128 + rl1] = __half_as_ushort(__float2half_rn(a3));
                }
            }
        }
    }

    if (vhalf) {
        __syncthreads();
        int h = bn >> 8;
        int b = bm / SS;
        int s0 = bm & (SS - 1);
        int vd = tid >> 1;
        int jp0 = (tid & 1) * 32;
        size_t base = ((size_t)((b * NHH + h) * VHDD + vd)) * (SS / 2) + (s0 >> 1) + jp0;
#pragma unroll
        for (int j = 0; j < 32; ++j) {
            uint32_t lo = st16[vd * 128 + 2 * (jp0 + j)];
            uint32_t hi = st16[vd * 128 + 2 * (jp0 + j) + 1];
            vb[base + j] = lo | (hi << 16);
        }
    }
}

// ============================================================================
// HMMA flash attention (causal), 1-pass fp16, 2 CTAs/SM (unchanged math)
// ============================================================================
#define FL_QS   0
#define FL_KS   6400
#define FL_VS   12800
#define FL_PS   17408
#define FL_RM   19712
#define FL_RL   19840
#define FL_WORDS 19968
#define FLASH_SMEM (FL_WORDS*4)

__global__ __launch_bounds__(256, 2) void flash_hmma(
    const uint32_t* __restrict__ qh_,
    const uint32_t* __restrict__ kh_,
    const uint32_t* __restrict__ vh_,
    uint32_t* __restrict__ aoh)
{
    cudaGridDependencySynchronize();
    extern __shared__ uint32_t sw[];
    float* redm = (float*)(sw + FL_RM);
    float* redl = (float*)(sw + FL_RL);
    const int tid = threadIdx.x;
    const int lane = tid & 31;
    const int wid = tid >> 5;
    const int wm = wid & 3, wn = wid >> 2;
    const int g = lane >> 2, t = lane & 3;
    const int qt = (int)(gridDim.x - 1) - (int)blockIdx.x;
    const int h = blockIdx.y, b = blockIdx.z;
    const int q0 = qt * 64;
    const int row0 = wm * 16 + g, row1 = row0 + 8;

    {
        int r = tid >> 2, qq = tid & 3;
        size_t gb = ((size_t)((b * SS + q0 + r) * NHH + h)) * 96 + qq * 24;
#pragma unroll
        for (int j = 0; j < 6; ++j)
            *(uint4*)(sw + FL_QS + r * 100 + qq * 24 + j * 4) = *(const uint4*)(qh_ + gb + j * 4);
    }

    float o[8][4];
#pragma unroll
    for (int i = 0; i < 8; i++)
#pragma unroll
        for (int j = 0; j < 4; j++) o[i][j] = 0.f;
    float mold0 = -1e30f, mold1 = -1e30f, ls0 = 0.f, ls1 = 0.f;

    for (int kt = 0; kt <= qt; ++kt) {
        const int k0 = kt * 64;
        __syncthreads();
        {
            int r = tid >> 2, qq = tid & 3;
            size_t gb = ((size_t)((b * SS + k0 + r) * NHH + h)) * 96 + qq * 24;
#pragma unroll
            for (int j = 0; j < 6; ++j)
                *(uint4*)(sw + FL_KS + r * 100 + qq * 24 + j * 4) = *(const uint4*)(kh_ + gb + j * 4);
            int vd = tid >> 1, pt = tid & 1;
            size_t vb = ((size_t)((b * NHH + h) * VHDD + vd)) * (SS / 2) + kt * 32 + pt * 16;
#pragma unroll
            for (int j = 0; j < 4; ++j)
                *(uint4*)(sw + FL_VS + vd * 36 + pt * 16 + j * 4) = *(const uint4*)(vh_ + vb + j * 4);
        }
        __syncthreads();

        float sacc[4][4];
#pragma unroll
        for (int i = 0; i < 4; i++)
#pragma unroll
            for (int j = 0; j < 4; j++) sacc[i][j] = 0.f;
#pragma unroll
        for (int ks = 0; ks < 12; ++ks) {
            int aq = (wm * 16 + g) * 100 + ks * 8 + t;
            uint32_t ah[4];
            ah[0] = sw[FL_QS + aq];       ah[1] = sw[FL_QS + aq + 800];
            ah[2] = sw[FL_QS + aq + 4];   ah[3] = sw[FL_QS + aq + 804];
#pragma unroll
            for (int nt = 0; nt < 4; ++nt) {
                int bi = (wn * 32 + nt * 8 + g) * 100 + ks * 8 + t;
                uint32_t bh[2] = { sw[FL_KS + bi], sw[FL_KS + bi + 4] };
                mma_h(sacc[nt], ah, bh);
            }
        }

        const bool diag = (kt == qt);
#pragma unroll
        for (int nt = 0; nt < 4; ++nt) {
            sacc[nt][0] *= SCALE_V; sacc[nt][1] *= SCALE_V;
            sacc[nt][2] *= SCALE_V; sacc[nt][3] *= SCALE_V;
            if (diag) {
                int c0 = wn * 32 + nt * 8 + 2 * t;
                if (c0 > row0)     sacc[nt][0] = -1e30f;
                if (c0 + 1 > row0) sacc[nt][1] = -1e30f;
                if (c0 > row1)     sacc[nt][2] = -1e30f;
                if (c0 + 1 > row1) sacc[nt][3] = -1e30f;
            }
        }

        float m0 = -1e30f, m1 = -1e30f;
#pragma unroll
        for (int nt = 0; nt < 4; ++nt) {
            m0 = fmaxf(m0, fmaxf(sacc[nt][0], sacc[nt][1]));
            m1 = fmaxf(m1, fmaxf(sacc[nt][2], sacc[nt][3]));
        }
        m0 = fmaxf(m0, __shfl_xor_sync(0xffffffffu, m0, 1));
        m0 = fmaxf(m0, __shfl_xor_sync(0xffffffffu, m0, 2));
        m1 = fmaxf(m1, __shfl_xor_sync(0xffffffffu, m1, 1));
        m1 = fmaxf(m1, __shfl_xor_sync(0xffffffffu, m1, 2));
        if (t == 0) { redm[wn * 64 + row0] = m0; redm[wn * 64 + row1] = m1; }
        __syncthreads();

        float mnew0 = fmaxf(mold0, fmaxf(redm[row0], redm[64 + row0]));
        float mnew1 = fmaxf(mold1, fmaxf(redm[row1], redm[64 + row1]));
        float fac0 = __expf(mold0 - mnew0);
        float fac1 = __expf(mold1 - mnew1);
        mold0 = mnew0; mold1 = mnew1;

        float sum0 = 0.f, sum1 = 0.f;
#pragma unroll
        for (int nt = 0; nt < 4; ++nt) {
            float p0 = __expf(sacc[nt][0] - mnew0);
            float p1 = __expf(sacc[nt][1] - mnew0);
            float p2 = __expf(sacc[nt][2] - mnew1);
            float p3 = __expf(sacc[nt][3] - mnew1);
            sum0 += p0 + p1; sum1 += p2 + p3;
            sw[FL_PS + row0 * 36 + wn * 16 + nt * 4 + t] = pack_h(p0, p1);
            sw[FL_PS + row1 * 36 + wn * 16 + nt * 4 + t] = pack_h(p2, p3);
        }
        sum0 += __shfl_xor_sync(0xffffffffu, sum0, 1);
        sum0 += __shfl_xor_sync(0xffffffffu, sum0, 2);
        sum1 += __shfl_xor_sync(0xffffffffu, sum1, 1);
        sum1 += __shfl_xor_sync(0xffffffffu, sum1, 2);
        if (t == 0) { redl[wn * 64 + row0] = sum0; redl[wn * 64 + row1] = sum1; }

#pragma unroll
        for (int nt = 0; nt < 8; ++nt) {
            o[nt][0] *= fac0; o[nt][1] *= fac0;
            o[nt][2] *= fac1; o[nt][3] *= fac1;
        }
        __syncthreads();

        ls0 = ls0 * fac0 + redl[row0] + redl[64 + row0];
        ls1 = ls1 * fac1 + redl[row1] + redl[64 + row1];

#pragma unroll
        for (int ks = 0; ks < 4; ++ks) {
            int pb = (wm * 16 + g) * 36 + ks * 8 + t;
            uint32_t ah[4];
            ah[0] = sw[FL_PS + pb];       ah[1] = sw[FL_PS + pb + 288];
            ah[2] = sw[FL_PS + pb + 4];   ah[3] = sw[FL_PS + pb + 292];
#pragma unroll
            for (int nt = 0; nt < 8; ++nt) {
                int vi = (wn * 64 + nt * 8 + g) * 36 + ks * 8 + t;
                uint32_t bh[2] = { sw[FL_VS + vi], sw[FL_VS + vi + 4] };
                mma_h(o[nt], ah, bh);
            }
        }
    }

    float inv0 = 1.0f / ls0, inv1 = 1.0f / ls1;
    size_t r0 = (size_t)(b * SS + q0 + row0) * 1024;
    size_t r1 = (size_t)(b * SS + q0 + row1) * 1024;
#pragma unroll
    for (int nt = 0; nt < 8; ++nt) {
        int word = h * 64 + wn * 32 + nt * 4 + t;
        aoh[r0 + word] = pack_h(o[nt][0] * inv0, o[nt][1] * inv0);
        aoh[r1 + word] = pack_h(o[nt][2] * inv1, o[nt][3] * inv1);
    }
}

// ============================================================================
// launch (all kernels with PDL attribute)
// ============================================================================
extern "C" void kernel_launch(void* const* d_in, const int* in_sizes, int n_in,
                              void* d_out, int out_size)
{
    const float* x         = (const float*)d_in[0];
    const float* fcos      = (const float*)d_in[1];
    const float* fsin      = (const float*)d_in[2];
    const float* wq_a_w    = (const float*)d_in[3];
    const float* wq_a_b    = (const float*)d_in[4];
    const float* q_norm_w  = (const float*)d_in[5];
    const float* wq_b_w    = (const float*)d_in[6];
    const float* wq_b_b    = (const float*)d_in[7];
    const float* wkv_a_w   = (const float*)d_in[8];
    const float* wkv_a_b   = (const float*)d_in[9];
    const float* kv_norm_w = (const float*)d_in[10];
    const float* wkv_b_w   = (const float*)d_in[11];
    const float* wkv_b_b   = (const float*)d_in[12];
    const float* wo_w      = (const float*)d_in[13];
    const float* wo_b      = (const float*)d_in[14];
    float* out = (float*)d_out;

    float *qa, *kva;
    uint32_t *xh, *wa, *wqb, *wkvb, *wo16, *qah, *kvah, *qb, *kb, *vb, *aoh;
    cudaGetSymbolAddress((void**)&qa,   g_qa);
    cudaGetSymbolAddress((void**)&kva,  g_kva);
    cudaGetSymbolAddress((void**)&xh,   g_xh);
    cudaGetSymbolAddress((void**)&wa,   g_wa);
    cudaGetSymbolAddress((void**)&wqb,  g_wqb);
    cudaGetSymbolAddress((void**)&wkvb, g_wkvb);
    cudaGetSymbolAddress((void**)&wo16, g_wo);
    cudaGetSymbolAddress((void**)&qah,  g_qah);
    cudaGetSymbolAddress((void**)&kvah, g_kvah);
    cudaGetSymbolAddress((void**)&qb,   g_qb);
    cudaGetSymbolAddress((void**)&kb,   g_kb);
    cudaGetSymbolAddress((void**)&vb,   g_vb);
    cudaGetSymbolAddress((void**)&aoh,  g_aoh);

    cudaFuncSetAttribute(gemm_hmma,   cudaFuncAttributeMaxDynamicSharedMemorySize, GEMM_SMEM);
    cudaFuncSetAttribute(gemm34_hmma, cudaFuncAttributeMaxDynamicSharedMemorySize, GEMM_SMEM);
    cudaFuncSetAttribute(flash_hmma,  cudaFuncAttributeMaxDynamicSharedMemorySize, FLASH_SMEM);

    cudaLaunchAttribute at;
    at.id = cudaLaunchAttributeProgrammaticStreamSerialization;
    at.val.programmaticStreamSerializationAllowed = 1;

    cudaLaunchConfig_t cfg = {};
    cfg.blockDim = dim3(256, 1, 1);
    cfg.stream = 0;
    cfg.attrs = &at;
    cfg.numAttrs = 1;

    // 1) all fp32->fp16 conversions (one launch)
    cfg.gridDim = dim3(CB5, 1, 1);
    cfg.dynamicSmemBytes = 0;
    cudaLaunchKernelEx(&cfg, cvt_all_k,
        x, xh, wq_a_w, wa, wkv_a_w, (uint32_t*)(wa + QLORA * (DIMD/2)),
        wq_b_w, wqb, wkv_b_w, wkvb, wo_w, wo16);

    // 2) fused gemm1+2
    cfg.gridDim = dim3((QLORA + KVAW + 127) / 128, ROWS / 128, 1);
    cfg.dynamicSmemBytes = GEMM_SMEM;
    cudaLaunchKernelEx(&cfg, gemm_hmma,
        (const uint32_t*)xh, (int)(DIMD/2), (const uint32_t*)wa, wq_a_b,
        qa, (int)(QLORA + KVAW), (int)DIMD, 2, wkv_a_b, kva);

    // 3) fused rmsnorm + roped-kpe broadcast
    cfg.gridDim = dim3(2 * ROWS + (ROWS * 32) / 256, 1, 1);
    cfg.dynamicSmemBytes = 0;
    cudaLaunchKernelEx(&cfg, norm_rope_k,
        (const float*)qa, q_norm_w, qah, (const float*)kva, kv_norm_w, kvah,
        fcos, fsin, kb);

    // 4) fused gemm3+gemm4
    cfg.gridDim = dim3(768 + 1024, 1, 1);
    cfg.dynamicSmemBytes = GEMM_SMEM;
    cudaLaunchKernelEx(&cfg, gemm34_hmma,
        (const uint32_t*)qah, (const uint32_t*)wqb, wq_b_b, qb,
        (const uint32_t*)kvah, (const uint32_t*)wkvb, wkv_b_b, kb, vb,
        fcos, fsin);

    // 5) flash attention
    cfg.gridDim = dim3(SS / 64, NHH, BB);
    cfg.dynamicSmemBytes = FLASH_SMEM;
    cudaLaunchKernelEx(&cfg, flash_hmma,
        (const uint32_t*)qb, (const uint32_t*)kb, (const uint32_t*)vb, aoh);

    // 6) gemm5
    cfg.gridDim = dim3(DIMD / 128, ROWS / 128, 1);
    cfg.dynamicSmemBytes = GEMM_SMEM;
    cudaLaunchKernelEx(&cfg, gemm_hmma,
        (const uint32_t*)aoh, (int)((NHH*VHDD)/2), (const uint32_t*)wo16, wo_b,
        out, (int)DIMD, (int)DIMD, 0, (const float*)nullptr, (float*)nullptr);
}

// round 16
// speedup vs baseline: 1.2393x; 1.0632x over previous
#include <cuda_runtime.h>
#include <cuda_fp16.h>
#include <cstdint>
#include <math.h>

// ---------------- problem constants ----------------
#define BB      2
#define SS      2048
#define DIMD    2048
#define NHH     16
#define QLORA   1536
#define KVLORA  512
#define ROPED   64
#define NOPED   128
#define VHDD    128
#define QKHD    192
#define KVAW    576
#define ROWS    (BB*SS)
#define SCALE_V 0.07216878364870323f

// ---------------- scratch (device globals) ----------------
__device__ float g_qa [ROWS * QLORA];
__device__ float g_kva[ROWS * KVAW];
__device__ uint32_t g_xh  [ROWS * 1024];
__device__ uint32_t g_wa  [(QLORA + KVAW) * (DIMD/2)];
__device__ uint32_t g_wqb [(NHH*QKHD) * (QLORA/2)];
__device__ uint32_t g_wkvb[(NHH*(NOPED+VHDD)) * (KVLORA/2)];
__device__ uint32_t g_wo  [DIMD * ((NHH*VHDD)/2)];
__device__ uint32_t g_qah [ROWS * 768];
__device__ uint32_t g_kvah[ROWS * 256];
__device__ uint32_t g_aoh [ROWS * 1024];
__device__ uint32_t g_qb  [ROWS * NHH * 96];
__device__ uint32_t g_kb  [ROWS * NHH * 96];
__device__ uint32_t g_vb  [BB * NHH * VHDD * (SS/2)];

// ============================================================================
// helpers
// ============================================================================
__device__ __forceinline__ uint32_t pack_h(float a, float b) {
    uint16_t lo16 = __half_as_ushort(__float2half_rn(a));
    uint16_t hi16 = __half_as_ushort(__float2half_rn(b));
    return (uint32_t)lo16 | ((uint32_t)hi16 << 16);
}
__device__ __forceinline__ void mma_h(float* d, const uint32_t* a, const uint32_t* b) {
    asm volatile(
        "mma.sync.aligned.m16n8k16.row.col.f32.f16.f16.f32 "
        "{%0,%1,%2,%3}, {%4,%5,%6,%7}, {%8,%9}, {%0,%1,%2,%3};"
        : "+f"(d[0]), "+f"(d[1]), "+f"(d[2]), "+f"(d[3])
        : "r"(a[0]), "r"(a[1]), "r"(a[2]), "r"(a[3]), "r"(b[0]), "r"(b[1]));
}
__device__ __forceinline__ uint32_t smem_u32(const void* p) {
    uint32_t a;
    asm("{ .reg .u64 t; cvta.to.shared.u64 t, %1; cvt.u32.u64 %0, t; }" : "=r"(a) : "l"(p));
    return a;
}
__device__ __forceinline__ void ldsm_x4(uint32_t* r, uint32_t saddr) {
    asm volatile("ldmatrix.sync.aligned.m8n8.x4.shared.b16 {%0,%1,%2,%3}, [%4];"
        : "=r"(r[0]), "=r"(r[1]), "=r"(r[2]), "=r"(r[3]) : "r"(saddr));
}
#define CP16(dst, src, sz) \
    asm volatile("cp.async.ca.shared.global [%0], [%1], 16, %2;" :: "r"(dst), "l"(src), "r"(sz))
#define CP_COMMIT() asm volatile("cp.async.commit_group;")
#define CP_WAIT1()  asm volatile("cp.async.wait_group 1;" ::: "memory")

// ============================================================================
// merged conversion kernel (unchanged)
// ============================================================================
#define CB0 2048
#define CB1 (CB0+768)
#define CB2 (CB1+288)
#define CB3 (CB2+1152)
#define CB4 (CB3+512)
#define CB5 (CB4+1024)

__global__ void cvt_all_k(
    const float* __restrict__ s0, uint32_t* __restrict__ d0,
    const float* __restrict__ s1, uint32_t* __restrict__ d1,
    const float* __restrict__ s2, uint32_t* __restrict__ d2,
    const float* __restrict__ s3, uint32_t* __restrict__ d3,
    const float* __restrict__ s4, uint32_t* __restrict__ d4,
    const float* __restrict__ s5, uint32_t* __restrict__ d5)
{
    cudaGridDependencySynchronize();
    int b = blockIdx.x;
    const float* src; uint32_t* dst; int base;
    if      (b < CB0) { src = s0; dst = d0; base = 0;   }
    else if (b < CB1) { src = s1; dst = d1; base = CB0; }
    else if (b < CB2) { src = s2; dst = d2; base = CB1; }
    else if (b < CB3) { src = s3; dst = d3; base = CB2; }
    else if (b < CB4) { src = s4; dst = d4; base = CB3; }
    else              { src = s5; dst = d5; base = CB4; }
    size_t i0 = ((size_t)(b - base) * 256 + threadIdx.x) * 4;
    float4 v[4];
#pragma unroll
    for (int j = 0; j < 4; ++j) v[j] = *(const float4*)(src + 4 * (i0 + j));
#pragma unroll
    for (int j = 0; j < 4; ++j) {
        uint2 hi;
        hi.x = pack_h(v[j].x, v[j].y);
        hi.y = pack_h(v[j].z, v[j].w);
        *(uint2*)(dst + 2 * (i0 + j)) = hi;
    }
}

// ============================================================================
// fused norm+rope (unchanged math)
// ============================================================================
__global__ __launch_bounds__(256) void norm_rope_k(
    const float* __restrict__ qa, const float* __restrict__ qnw, uint32_t* __restrict__ qah,
    const float* __restrict__ kva, const float* __restrict__ kvnw, uint32_t* __restrict__ kvah,
    const float* __restrict__ cosd, const float* __restrict__ sind, uint32_t* __restrict__ kb)
{
    cudaGridDependencySynchronize();
    int bx = blockIdx.x;
    if (bx >= 2 * ROWS) {
        int i = (bx - 2 * ROWS) * 256 + threadIdx.x;
        int wp = i & 31;
        int bs = i >> 5;
        int s = bs & (SS - 1);
        float2 v = *(const float2*)(kva + (size_t)bs * KVAW + KVLORA + 2 * wp);
        float c = cosd[s * 32 + wp], sn = sind[s * 32 + wp];
        uint32_t w = pack_h(v.x * c - v.y * sn, v.x * sn + v.y * c);
        uint32_t* dst = kb + (size_t)bs * 1536 + 64 + wp;
#pragma unroll
        for (int h = 0; h < 16; ++h) dst[h * 96] = w;
        return;
    }
    const bool isq = bx < ROWS;
    const int rix = isq ? bx : bx - ROWS;
    const float* row = (isq ? qa : kva) + (size_t)rix * (isq ? QLORA : KVAW);
    const float* w   = isq ? qnw : kvnw;
    uint32_t* oh     = isq ? qah : kvah;
    const int n      = isq ? QLORA : KVLORA;

    float ss = 0.f;
    for (int i = threadIdx.x * 4; i < n; i += 1024) {
        float4 v = *(const float4*)(row + i);
        ss += v.x * v.x + v.y * v.y + v.z * v.z + v.w * v.w;
    }
#pragma unroll
    for (int off = 16; off; off >>= 1) ss += __shfl_xor_sync(0xffffffffu, ss, off);
    __shared__ float ws[8];
    if ((threadIdx.x & 31) == 0) ws[threadIdx.x >> 5] = ss;
    __syncthreads();
    float tot = 0.f;
#pragma unroll
    for (int i = 0; i < 8; i++) tot += ws[i];
    float r = rsqrtf(tot / (float)n + 1e-6f);
    const int ow = n >> 1;
    for (int i = threadIdx.x * 4; i < n; i += 1024) {
        float4 v  = *(const float4*)(row + i);
        float4 wv = *(const float4*)(w + i);
        v.x *= r * wv.x; v.y *= r * wv.y; v.z *= r * wv.z; v.w *= r * wv.w;
        uint2 hi;
        hi.x = pack_h(v.x, v.y);
        hi.y = pack_h(v.z, v.w);
        *(uint2*)(oh + (size_t)rix * ow + (i >> 1)) = hi;
    }
}

// ============================================================================
// GEMM core: CTA 128x128, 8 warps (2m x 4n), K-chunk 32, cp.async 3-stage,
// ldmatrix fragment loads, 2 CTAs/SM.
// ============================================================================
#define ASZW   2560
#define STAGEW (2*ASZW)
#define GEMM_SMEM (3*STAGEW*4)

#define GEMM_ISSUE(S, CK) do {                                   \
    uint32_t stb_ = sbB + (uint32_t)(S) * (STAGEW * 4);          \
    int k0w_ = (CK) << 4;                                        \
    CP16(stb_ + adst0, ar0 + k0w_, 16u);                         \
    CP16(stb_ + adst1, ar1 + k0w_, 16u);                         \
    CP16(stb_ + bdst0, br0 + k0w_, sz0);                         \
    CP16(stb_ + bdst1, br1 + k0w_, sz1);                         \
} while (0)

#define GEMM_MAINLOOP(ACC)                                                      \
    const uint32_t sbB = smem_u32(smw);                                         \
    const int lane15 = lane & 15;                                               \
    const int lhi = lane >> 4;                                                  \
    const uint32_t aoff0 = ((warp_m * 64 + lane15) * 20 + lhi * 4) * 4;         \
    const uint32_t boff0 = (ASZW + (warp_n * 32 + lane15) * 20 + lhi * 4) * 4;  \
    const uint32_t adst0 = (lr * 20 + lq * 4) * 4;                              \
    const uint32_t adst1 = ((lr + 64) * 20 + lq * 4) * 4;                       \
    const uint32_t bdst0 = (ASZW + lr * 20 + lq * 4) * 4;                       \
    const uint32_t bdst1 = (ASZW + (lr + 64) * 20 + lq * 4) * 4;                \
    const uint32_t* ar0 = Ah_ + (size_t)(bm + lr) * ldaw + lq * 4;              \
    const uint32_t* ar1 = Ah_ + (size_t)(bm + lr + 64) * ldaw + lq * 4;         \
    const uint32_t* br0 = Bh_ + (size_t)(bv0 ? (bn + lr) : 0) * ldbw + lq * 4;  \
    const uint32_t* br1 = Bh_ + (size_t)(bv1 ? (bn + lr + 64) : 0) * ldbw + lq * 4; \
    const uint32_t sz0 = bv0 ? 16u : 0u, sz1 = bv1 ? 16u : 0u;                  \
    GEMM_ISSUE(0, 0); CP_COMMIT();                                              \
    if (nc > 1) { GEMM_ISSUE(1, 1); } CP_COMMIT();                              \
    CP_WAIT1(); __syncthreads();                                                \
    for (int ck = 0; ck < nc; ++ck) {                                           \
        {                                                                       \
            const uint32_t stb = sbB + (uint32_t)(ck % 3) * (STAGEW * 4);       \
            _Pragma("unroll")                                                   \
            for (int k16 = 0; k16 < 2; ++k16) {                                 \
                const uint32_t kb4 = k16 * 32;                                  \
                uint32_t bfr[2][4];                                             \
                ldsm_x4(bfr[0], stb + boff0 + kb4);                             \
                ldsm_x4(bfr[1], stb + boff0 + 1280 + kb4);                      \
                _Pragma("unroll")                                               \
                for (int mt = 0; mt < 4; ++mt) {                                \
                    uint32_t ah[4];                                             \
                    ldsm_x4(ah, stb + aoff0 + mt * 1280 + kb4);                 \
                    _Pragma("unroll")                                           \
                    for (int ntp = 0; ntp < 2; ++ntp) {                         \
                        uint32_t b0[2] = { bfr[ntp][0], bfr[ntp][2] };          \
                        uint32_t b1[2] = { bfr[ntp][1], bfr[ntp][3] };          \
                        mma_h(ACC[mt][2*ntp],   ah, b0);                        \
                        mma_h(ACC[mt][2*ntp+1], ah, b1);                        \
                    }                                                           \
                }                                                               \
            }                                                                   \
        }                                                                       \
        if (ck + 2 < nc) { GEMM_ISSUE((ck + 2) % 3, ck + 2); }                  \
        CP_COMMIT(); CP_WAIT1();                                                \
        __syncthreads();                                                        \
    }

#define GEMM_PREAMBLE(NN, KK)                        \
    extern __shared__ uint32_t smw[];                \
    const int tid  = threadIdx.x;                    \
    const int lane = tid & 31;                       \
    const int wid  = tid >> 5;                       \
    const int warp_m = wid & 1;                      \
    const int warp_n = wid >> 1;                     \
    const int t = lane & 3;                          \
    const int g = lane >> 2;                         \
    const int ldbw = (KK) >> 1;                      \
    const int nc = (KK) >> 5;                        \
    const int lr = tid >> 2;                         \
    const int lq = tid & 3;                          \
    const bool bv0 = (bn + lr) < (NN);               \
    const bool bv1 = (bn + lr + 64) < (NN);          \
    float acc[4][4][4];                              \
    _Pragma("unroll")                                \
    for (int i = 0; i < 4; i++)                      \
        _Pragma("unroll")                            \
        for (int j = 0; j < 4; j++)                  \
            _Pragma("unroll")                        \
            for (int k = 0; k < 4; k++) acc[i][j][k] = 0.f;

// ---- gemm_hmma: mode 0 (plain) / mode 2 (dual qa|kva) ----
__global__ __launch_bounds__(256, 2) void gemm_hmma(
    const uint32_t* __restrict__ Ah_, int ldaw,
    const uint32_t* __restrict__ Bh_,
    const float* __restrict__ bias,
    float* __restrict__ C, int N, int K,
    int mode,
    const float* __restrict__ bias2, float* __restrict__ C2)
{
    cudaGridDependencySynchronize();
    const int bm = blockIdx.y * 128;
    const int bn = blockIdx.x * 128;
    GEMM_PREAMBLE(N, K)
    GEMM_MAINLOOP(acc)

#pragma unroll
    for (int mt = 0; mt < 4; ++mt) {
        int r0 = bm + warp_m * 64 + mt * 16 + g;
        int r1 = r0 + 8;
#pragma unroll
        for (int nt = 0; nt < 4; ++nt) {
            int c = bn + warp_n * 32 + nt * 8 + t * 2;
            if (c >= N) continue;
            float a0 = acc[mt][nt][0], a1 = acc[mt][nt][1];
            float a2 = acc[mt][nt][2], a3 = acc[mt][nt][3];
            if (mode == 0) {
                float2 bv = *(const float2*)(bias + c);
                a0 += bv.x; a1 += bv.y; a2 += bv.x; a3 += bv.y;
                *(float2*)(C + (size_t)r0 * N + c) = make_float2(a0, a1);
                *(float2*)(C + (size_t)r1 * N + c) = make_float2(a2, a3);
            } else {
                if (c < QLORA) {
                    float2 bv = *(const float2*)(bias + c);
                    a0 += bv.x; a1 += bv.y; a2 += bv.x; a3 += bv.y;
                    *(float2*)(C + (size_t)r0 * QLORA + c) = make_float2(a0, a1);
                    *(float2*)(C + (size_t)r1 * QLORA + c) = make_float2(a2, a3);
                } else {
                    int c2 = c - QLORA;
                    float2 bv = *(const float2*)(bias2 + c2);
                    a0 += bv.x; a1 += bv.y; a2 += bv.x; a3 += bv.y;
                    *(float2*)(C2 + (size_t)r0 * KVAW + c2) = make_float2(a0, a1);
                    *(float2*)(C2 + (size_t)r1 * KVAW + c2) = make_float2(a2, a3);
                }
            }
        }
    }
}

// ---- gemm34: flattened 1D grid; bid<768 -> q path; else kv path ----
__global__ __launch_bounds__(256, 2) void gemm34_hmma(
    const uint32_t* __restrict__ A3, const uint32_t* __restrict__ B3,
    const float* __restrict__ bias3, uint32_t* __restrict__ qb,
    const uint32_t* __restrict__ A4, const uint32_t* __restrict__ B4,
    const float* __restrict__ bias4, uint32_t* __restrict__ kb, uint32_t* __restrict__ vb,
    const float* __restrict__ cosd, const float* __restrict__ sind)
{
    cudaGridDependencySynchronize();
    const int bid = blockIdx.x;
    const int z = (bid >= 768);
    int bx, by;
    if (!z) { bx = bid % 24; by = bid / 24; }
    else    { int r = bid - 768; bx = r & 31; by = r >> 5; }
    const int bm = by * 128;
    const int bn = bx * 128;

    const uint32_t* Ah_ = z ? A4 : A3;
    const uint32_t* Bh_ = z ? B4 : B3;
    const float* bias   = z ? bias4 : bias3;
    const int ldaw = z ? (KVLORA / 2) : (QLORA / 2);
    const int N    = z ? (NHH * (NOPED + VHDD)) : (NHH * QKHD);
    const int K    = z ? KVLORA : QLORA;

    GEMM_PREAMBLE(N, K)
    GEMM_MAINLOOP(acc)

    uint16_t* st16 = (uint16_t*)smw;
    const bool vhalf = z && ((bn >> 7) & 1);

#pragma unroll
    for (int mt = 0; mt < 4; ++mt) {
        int r0 = bm + warp_m * 64 + mt * 16 + g;
        int r1 = r0 + 8;
#pragma unroll
        for (int nt = 0; nt < 4; ++nt) {
            int c = bn + warp_n * 32 + nt * 8 + t * 2;
            float2 bv = *(const float2*)(bias + c);
            float a0 = acc[mt][nt][0] + bv.x, a1 = acc[mt][nt][1] + bv.y;
            float a2 = acc[mt][nt][2] + bv.x, a3 = acc[mt][nt][3] + bv.y;
            if (!z) {
                int d = c % 192;
                if (d >= 128) {
                    int ri = (d - 128) >> 1;
                    int s0 = r0 & (SS - 1), s1 = r1 & (SS - 1);
                    float c0 = cosd[s0 * 32 + ri], n0 = sind[s0 * 32 + ri];
                    float c1 = cosd[s1 * 32 + ri], n1 = sind[s1 * 32 + ri];
                    float x0 = a0, y0 = a1, x1 = a2, y1 = a3;
                    a0 = x0 * c0 - y0 * n0;  a1 = x0 * n0 + y0 * c0;
                    a2 = x1 * c1 - y1 * n1;  a3 = x1 * n1 + y1 * c1;
                }
                qb[(size_t)r0 * 1536 + (c >> 1)] = pack_h(a0, a1);
                qb[(size_t)r1 * 1536 + (c >> 1)] = pack_h(a2, a3);
            } else {
                int blk = c & 255;
                if (blk < 128) {
                    int hh = c >> 8;
                    kb[(size_t)r0 * 1536 + hh * 96 + (blk >> 1)] = pack_h(a0, a1);
                    kb[(size_t)r1 * 1536 + hh * 96 + (blk >> 1)] = pack_h(a2, a3);
                } else {
                    int cl = c & 127;
                    int rl0 = r0 - bm, rl1 = r1 - bm;
                    st16[(cl + 0) * 128 + rl0] = __half_as_ushort(__float2half_rn(a0));
                    st16[(cl + 1) * 128 + rl0] = __half_as_ushort(__float2half_rn(a1));
                    st16[(cl + 0) * 128 + rl1] = __half_as_ushort(__float2half_rn(a2));
                    st16[(cl + 1) * 128 + rl1] = __half_as_ushort(__float2half_rn(a3));
                }
            }
        }
    }

    if (vhalf) {
        __syncthreads();
        int h = bn >> 8;
        int b = bm / SS;
        int s0 = bm & (SS - 1);
        int vd = tid >> 1;
        int jp0 = (tid & 1) * 32;
        size_t base = ((size_t)((b * NHH + h) * VHDD + vd)) * (SS / 2) + (s0 >> 1) + jp0;
#pragma unroll
        for (int j = 0; j < 32; ++j) {
            uint32_t lo = st16[vd * 128 + 2 * (jp0 + j)];
            uint32_t hi = st16[vd * 128 + 2 * (jp0 + j) + 1];
            vb[base + j] = lo | (hi << 16);
        }
    }
}

// ============================================================================
// HMMA flash attention (causal), 1-pass fp16, 2 CTAs/SM, ldmatrix frag loads
// ============================================================================
#define FL_QS   0
#define FL_KS   6400
#define FL_VS   12800
#define FL_PS   17408
#define FL_RM   19712
#define FL_RL   19840
#define FL_WORDS 19968
#define FLASH_SMEM (FL_WORDS*4)

__global__ __launch_bounds__(256, 2) void flash_hmma(
    const uint32_t* __restrict__ qh_,
    const uint32_t* __restrict__ kh_,
    const uint32_t* __restrict__ vh_,
    uint32_t* __restrict__ aoh)
{
    cudaGridDependencySynchronize();
    extern __shared__ uint32_t sw[];
    float* redm = (float*)(sw + FL_RM);
    float* redl = (float*)(sw + FL_RL);
    const int tid = threadIdx.x;
    const int lane = tid & 31;
    const int wid = tid >> 5;
    const int wm = wid & 3, wn = wid >> 2;
    const int g = lane >> 2, t = lane & 3;
    const int lane15 = lane & 15;
    const int lhi = lane >> 4;
    const int qt = (int)(gridDim.x - 1) - (int)blockIdx.x;
    const int h = blockIdx.y, b = blockIdx.z;
    const int q0 = qt * 64;
    const int row0 = wm * 16 + g, row1 = row0 + 8;

    const uint32_t swB = smem_u32(sw);
    const uint32_t aoffQ = ((wm * 16 + lane15) * 100 + lhi * 4) * 4;
    const uint32_t boffK = (FL_KS + (wn * 32 + lane15) * 100 + lhi * 4) * 4;
    const uint32_t aoffP = (FL_PS + (wm * 16 + lane15) * 36 + lhi * 4) * 4;
    const uint32_t boffV = (FL_VS + (wn * 64 + lane15) * 36 + lhi * 4) * 4;

    {
        int r = tid >> 2, qq = tid & 3;
        size_t gb = ((size_t)((b * SS + q0 + r) * NHH + h)) * 96 + qq * 24;
#pragma unroll
        for (int j = 0; j < 6; ++j)
            *(uint4*)(sw + FL_QS + r * 100 + qq * 24 + j * 4) = *(const uint4*)(qh_ + gb + j * 4);
    }

    float o[8][4];
#pragma unroll
    for (int i = 0; i < 8; i++)
#pragma unroll
        for (int j = 0; j < 4; j++) o[i][j] = 0.f;
    float mold0 = -1e30f, mold1 = -1e30f, ls0 = 0.f, ls1 = 0.f;

    for (int kt = 0; kt <= qt; ++kt) {
        const int k0 = kt * 64;
        __syncthreads();
        {
            int r = tid >> 2, qq = tid & 3;
            size_t gb = ((size_t)((b * SS + k0 + r) * NHH + h)) * 96 + qq * 24;
#pragma unroll
            for (int j = 0; j < 6; ++j)
                *(uint4*)(sw + FL_KS + r * 100 + qq * 24 + j * 4) = *(const uint4*)(kh_ + gb + j * 4);
            int vd = tid >> 1, pt = tid & 1;
            size_t vb = ((size_t)((b * NHH + h) * VHDD + vd)) * (SS / 2) + kt * 32 + pt * 16;
#pragma unroll
            for (int j = 0; j < 4; ++j)
                *(uint4*)(sw + FL_VS + vd * 36 + pt * 16 + j * 4) = *(const uint4*)(vh_ + vb + j * 4);
        }
        __syncthreads();

        // ---- scores via ldmatrix
        float sacc[4][4];
#pragma unroll
        for (int i = 0; i < 4; i++)
#pragma unroll
            for (int j = 0; j < 4; j++) sacc[i][j] = 0.f;
#pragma unroll
        for (int ks = 0; ks < 12; ++ks) {
            const uint32_t kb4 = ks * 32;
            uint32_t ah[4];
            ldsm_x4(ah, swB + aoffQ + kb4);
            uint32_t bfr[2][4];
            ldsm_x4(bfr[0], swB + boffK + kb4);
            ldsm_x4(bfr[1], swB + boffK + 6400 + kb4);
#pragma unroll
            for (int ntp = 0; ntp < 2; ++ntp) {
                uint32_t b0[2] = { bfr[ntp][0], bfr[ntp][2] };
                uint32_t b1[2] = { bfr[ntp][1], bfr[ntp][3] };
                mma_h(sacc[2*ntp],   ah, b0);
                mma_h(sacc[2*ntp+1], ah, b1);
            }
        }

        const bool diag = (kt == qt);
#pragma unroll
        for (int nt = 0; nt < 4; ++nt) {
            sacc[nt][0] *= SCALE_V; sacc[nt][1] *= SCALE_V;
            sacc[nt][2] *= SCALE_V; sacc[nt][3] *= SCALE_V;
            if (diag) {
                int c0 = wn * 32 + nt * 8 + 2 * t;
                if (c0 > row0)     sacc[nt][0] = -1e30f;
                if (c0 + 1 > row0) sacc[nt][1] = -1e30f;
                if (c0 > row1)     sacc[nt][2] = -1e30f;
                if (c0 + 1 > row1) sacc[nt][3] = -1e30f;
            }
        }

        float m0 = -1e30f, m1 = -1e30f;
#pragma unroll
        for (int nt = 0; nt < 4; ++nt) {
            m0 = fmaxf(m0, fmaxf(sacc[nt][0], sacc[nt][1]));
            m1 = fmaxf(m1, fmaxf(sacc[nt][2], sacc[nt][3]));
        }
        m0 = fmaxf(m0, __shfl_xor_sync(0xffffffffu, m0, 1));
        m0 = fmaxf(m0, __shfl_xor_sync(0xffffffffu, m0, 2));
        m1 = fmaxf(m1, __shfl_xor_sync(0xffffffffu, m1, 1));
        m1 = fmaxf(m1, __shfl_xor_sync(0xffffffffu, m1, 2));
        if (t == 0) { redm[wn * 64 + row0] = m0; redm[wn * 64 + row1] = m1; }
        __syncthreads();

        float mnew0 = fmaxf(mold0, fmaxf(redm[row0], redm[64 + row0]));
        float mnew1 = fmaxf(mold1, fmaxf(redm[row1], redm[64 + row1]));
        float fac0 = __expf(mold0 - mnew0);
        float fac1 = __expf(mold1 - mnew1);
        mold0 = mnew0; mold1 = mnew1;

        float sum0 = 0.f, sum1 = 0.f;
#pragma unroll
        for (int nt = 0; nt < 4; ++nt) {
            float p0 = __expf(sacc[nt][0] - mnew0);
            float p1 = __expf(sacc[nt][1] - mnew0);
            float p2 = __expf(sacc[nt][2] - mnew1);
            float p3 = __expf(sacc[nt][3] - mnew1);
            sum0 += p0 + p1; sum1 += p2 + p3;
            sw[FL_PS + row0 * 36 + wn * 16 + nt * 4 + t] = pack_h(p0, p1);
            sw[FL_PS + row1 * 36 + wn * 16 + nt * 4 + t] = pack_h(p2, p3);
        }
        sum0 += __shfl_xor_sync(0xffffffffu, sum0, 1);
        sum0 += __shfl_xor_sync(0xffffffffu, sum0, 2);
        sum1 += __shfl_xor_sync(0xffffffffu, sum1, 1);
        sum1 += __shfl_xor_sync(0xffffffffu, sum1, 2);
        if (t == 0) { redl[wn * 64 + row0] = sum0; redl[wn * 64 + row1] = sum1; }

#pragma unroll
        for (int nt = 0; nt < 8; ++nt) {
            o[nt][0] *= fac0; o[nt][1] *= fac0;
            o[nt][2] *= fac1; o[nt][3] *= fac1;
        }
        __syncthreads();

        ls0 = ls0 * fac0 + redl[row0] + redl[64 + row0];
        ls1 = ls1 * fac1 + redl[row1] + redl[64 + row1];

        // ---- PV via ldmatrix
#pragma unroll
        for (int ks = 0; ks < 4; ++ks) {
            const uint32_t kb4 = ks * 32;
            uint32_t ah[4];
            ldsm_x4(ah, swB + aoffP + kb4);
#pragma unroll
            for (int ntp = 0; ntp < 4; ++ntp) {
                uint32_t bfr[4];
                ldsm_x4(bfr, swB + boffV + ntp * 2304 + kb4);
                uint32_t b0[2] = { bfr[0], bfr[2] };
                uint32_t b1[2] = { bfr[1], bfr[3] };
                mma_h(o[2*ntp],   ah, b0);
                mma_h(o[2*ntp+1], ah, b1);
            }
        }
    }

    float inv0 = 1.0f / ls0, inv1 = 1.0f / ls1;
    size_t r0 = (size_t)(b * SS + q0 + row0) * 1024;
    size_t r1 = (size_t)(b * SS + q0 + row1) * 1024;
#pragma unroll
    for (int nt = 0; nt < 8; ++nt) {
        int word = h * 64 + wn * 32 + nt * 4 + t;
        aoh[r0 + word] = pack_h(o[nt][0] * inv0, o[nt][1] * inv0);
        aoh[r1 + word] = pack_h(o[nt][2] * inv1, o[nt][3] * inv1);
    }
}

// ============================================================================
// launch (all kernels with PDL attribute)
// ============================================================================
extern "C" void kernel_launch(void* const* d_in, const int* in_sizes, int n_in,
                              void* d_out, int out_size)
{
    const float* x         = (const float*)d_in[0];
    const float* fcos      = (const float*)d_in[1];
    const float* fsin      = (const float*)d_in[2];
    const float* wq_a_w    = (const float*)d_in[3];
    const float* wq_a_b    = (const float*)d_in[4];
    const float* q_norm_w  = (const float*)d_in[5];
    const float* wq_b_w    = (const float*)d_in[6];
    const float* wq_b_b    = (const float*)d_in[7];
    const float* wkv_a_w   = (const float*)d_in[8];
    const float* wkv_a_b   = (const float*)d_in[9];
    const float* kv_norm_w = (const float*)d_in[10];
    const float* wkv_b_w   = (const float*)d_in[11];
    const float* wkv_b_b   = (const float*)d_in[12];
    const float* wo_w      = (const float*)d_in[13];
    const float* wo_b      = (const float*)d_in[14];
    float* out = (float*)d_out;

    float *qa, *kva;
    uint32_t *xh, *wa, *wqb, *wkvb, *wo16, *qah, *kvah, *qb, *kb, *vb, *aoh;
    cudaGetSymbolAddress((void**)&qa,   g_qa);
    cudaGetSymbolAddress((void**)&kva,  g_kva);
    cudaGetSymbolAddress((void**)&xh,   g_xh);
    cudaGetSymbolAddress((void**)&wa,   g_wa);
    cudaGetSymbolAddress((void**)&wqb,  g_wqb);
    cudaGetSymbolAddress((void**)&wkvb, g_wkvb);
    cudaGetSymbolAddress((void**)&wo16, g_wo);
    cudaGetSymbolAddress((void**)&qah,  g_qah);
    cudaGetSymbolAddress((void**)&kvah, g_kvah);
    cudaGetSymbolAddress((void**)&qb,   g_qb);
    cudaGetSymbolAddress((void**)&kb,   g_kb);
    cudaGetSymbolAddress((void**)&vb,   g_vb);
    cudaGetSymbolAddress((void**)&aoh,  g_aoh);

    cudaFuncSetAttribute(gemm_hmma,   cudaFuncAttributeMaxDynamicSharedMemorySize, GEMM_SMEM);
    cudaFuncSetAttribute(gemm34_hmma, cudaFuncAttributeMaxDynamicSharedMemorySize, GEMM_SMEM);
    cudaFuncSetAttribute(flash_hmma,  cudaFuncAttributeMaxDynamicSharedMemorySize, FLASH_SMEM);

    cudaLaunchAttribute at;
    at.id = cudaLaunchAttributeProgrammaticStreamSerialization;
    at.val.programmaticStreamSerializationAllowed = 1;

    cudaLaunchConfig_t cfg = {};
    cfg.blockDim = dim3(256, 1, 1);
    cfg.stream = 0;
    cfg.attrs = &at;
    cfg.numAttrs = 1;

    // 1) all fp32->fp16 conversions (one launch)
    cfg.gridDim = dim3(CB5, 1, 1);
    cfg.dynamicSmemBytes = 0;
    cudaLaunchKernelEx(&cfg, cvt_all_k,
        x, xh, wq_a_w, wa, wkv_a_w, (uint32_t*)(wa + QLORA * (DIMD/2)),
        wq_b_w, wqb, wkv_b_w, wkvb, wo_w, wo16);

    // 2) fused gemm1+2
    cfg.gridDim = dim3((QLORA + KVAW + 127) / 128, ROWS / 128, 1);
    cfg.dynamicSmemBytes = GEMM_SMEM;
    cudaLaunchKernelEx(&cfg, gemm_hmma,
        (const uint32_t*)xh, (int)(DIMD/2), (const uint32_t*)wa, wq_a_b,
        qa, (int)(QLORA + KVAW), (int)DIMD, 2, wkv_a_b, kva);

    // 3) fused rmsnorm + roped-kpe broadcast
    cfg.gridDim = dim3(2 * ROWS + (ROWS * 32) / 256, 1, 1);
    cfg.dynamicSmemBytes = 0;
    cudaLaunchKernelEx(&cfg, norm_rope_k,
        (const float*)qa, q_norm_w, qah, (const float*)kva, kv_norm_w, kvah,
        fcos, fsin, kb);

    // 4) fused gemm3+gemm4
    cfg.gridDim = dim3(768 + 1024, 1, 1);
    cfg.dynamicSmemBytes = GEMM_SMEM;
    cudaLaunchKernelEx(&cfg, gemm34_hmma,
        (const uint32_t*)qah, (const uint32_t*)wqb, wq_b_b, qb,
        (const uint32_t*)kvah, (const uint32_t*)wkvb, wkv_b_b, kb, vb,
        fcos, fsin);

    // 5) flash attention
    cfg.gridDim = dim3(SS / 64, NHH, BB);
    cfg.dynamicSmemBytes = FLASH_SMEM;
    cudaLaunchKernelEx(&cfg, flash_hmma,
        (const uint32_t*)qb, (const uint32_t*)kb, (const uint32_t*)vb, aoh);

    // 6) gemm5
    cfg.gridDim = dim3(DIMD / 128, ROWS / 128, 1);
    cfg.dynamicSmemBytes = GEMM_SMEM;
    cudaLaunchKernelEx(&cfg, gemm_hmma,
        (const uint32_t*)aoh, (int)((NHH*VHDD)/2), (const uint32_t*)wo16, wo_b,
        out, (int)DIMD, (int)DIMD, 0, (const float*)nullptr, (float*)nullptr);
}